// round 1
// baseline (speedup 1.0000x reference)
#include <cuda_runtime.h>
#include <cuda_bf16.h>
#include <cstdint>

// Problem constants
#define BATCH   2
#define SEQ     2048
#define DMODEL  1024
#define HEADS   16
#define DK      64
#define ROWS    (BATCH * SEQ)          // 4096

// ---------------------------------------------------------------------------
// Scratch buffers (device globals: allocation-free, graph-capture safe)
// ---------------------------------------------------------------------------
__device__ float g_q[ROWS * DMODEL];
__device__ float g_k[ROWS * DMODEL];
__device__ float g_v[ROWS * DMODEL];
__device__ float g_attn[ROWS * DMODEL];

// ---------------------------------------------------------------------------
// GEMM: C[M,N] = A[M,K] @ B[N,K]^T   (both operands K-contiguous, "NT")
// 128x128 block tile, BK=16, 256 threads, 8x8 microtile per thread.
// M,N,K all divisible by tile sizes for this problem -> no bounds checks.
// ---------------------------------------------------------------------------
#define BM 128
#define BN 128
#define BK 16
#define GPAD 132   // smem row pitch (floats): keeps float4 alignment, few conflicts

__global__ __launch_bounds__(256, 2)
void gemm_nt(const float* __restrict__ A, const float* __restrict__ B,
             float* __restrict__ C, int M, int N, int K)
{
    __shared__ float As[BK][GPAD];
    __shared__ float Bs[BK][GPAD];

    const int tid = threadIdx.x;
    const int ty  = tid >> 4;          // 0..15
    const int tx  = tid & 15;          // 0..15
    const int rowBase = blockIdx.y * BM;
    const int colBase = blockIdx.x * BN;

    float acc[8][8];
#pragma unroll
    for (int i = 0; i < 8; i++)
#pragma unroll
        for (int j = 0; j < 8; j++) acc[i][j] = 0.f;

    for (int k0 = 0; k0 < K; k0 += BK) {
        // Load A/B tiles: 128 rows x 16 floats = 512 float4 each; 2 per thread.
#pragma unroll
        for (int it = 0; it < 2; it++) {
            int idx = tid + it * 256;      // 0..511
            int r   = idx >> 2;            // 0..127
            int c4  = (idx & 3) * 4;       // 0,4,8,12
            float4 va = *(const float4*)&A[(size_t)(rowBase + r) * K + k0 + c4];
            As[c4 + 0][r] = va.x; As[c4 + 1][r] = va.y;
            As[c4 + 2][r] = va.z; As[c4 + 3][r] = va.w;
            float4 vb = *(const float4*)&B[(size_t)(colBase + r) * K + k0 + c4];
            Bs[c4 + 0][r] = vb.x; Bs[c4 + 1][r] = vb.y;
            Bs[c4 + 2][r] = vb.z; Bs[c4 + 3][r] = vb.w;
        }
        __syncthreads();

#pragma unroll
        for (int k = 0; k < BK; k++) {
            float a[8], b[8];
            // float4-aligned smem reads (GPAD % 4 == 0)
            float4 a0 = *(const float4*)&As[k][ty * 8 + 0];
            float4 a1 = *(const float4*)&As[k][ty * 8 + 4];
            float4 b0 = *(const float4*)&Bs[k][tx * 8 + 0];
            float4 b1 = *(const float4*)&Bs[k][tx * 8 + 4];
            a[0]=a0.x; a[1]=a0.y; a[2]=a0.z; a[3]=a0.w;
            a[4]=a1.x; a[5]=a1.y; a[6]=a1.z; a[7]=a1.w;
            b[0]=b0.x; b[1]=b0.y; b[2]=b0.z; b[3]=b0.w;
            b[4]=b1.x; b[5]=b1.y; b[6]=b1.z; b[7]=b1.w;
#pragma unroll
            for (int i = 0; i < 8; i++)
#pragma unroll
                for (int j = 0; j < 8; j++)
                    acc[i][j] = fmaf(a[i], b[j], acc[i][j]);
        }
        __syncthreads();
    }

    // Store
#pragma unroll
    for (int i = 0; i < 8; i++) {
        float* crow = &C[(size_t)(rowBase + ty * 8 + i) * N + colBase + tx * 8];
        float4 v0 = make_float4(acc[i][0], acc[i][1], acc[i][2], acc[i][3]);
        float4 v1 = make_float4(acc[i][4], acc[i][5], acc[i][6], acc[i][7]);
        *(float4*)&crow[0] = v0;
        *(float4*)&crow[4] = v1;
    }
}

// ---------------------------------------------------------------------------
// Causal flash attention.
// Grid: (qb=SEQ/64, bh=BATCH*HEADS). 256 threads (16x16), 4x4 microtiles.
// Streaming softmax with per-row (m, l) in smem. d_k = 64 exactly one tile.
// ---------------------------------------------------------------------------
#define APITCH 68   // 64 + 4 pad
#define ATTN_SMEM (4 * 64 * APITCH * 4)   // Qs,Ks,Vs,Ls  = 69632 bytes

__global__ __launch_bounds__(256, 2)
void attn_kernel(const float* __restrict__ q, const float* __restrict__ k,
                 const float* __restrict__ v, float* __restrict__ out)
{
    extern __shared__ float sm[];
    float* Qs = sm;                    // [64][APITCH]
    float* Ks = Qs + 64 * APITCH;
    float* Vs = Ks + 64 * APITCH;
    float* Ls = Vs + 64 * APITCH;      // logits, then P = exp(...)

    __shared__ float mrow[64], lrow[64], arow[64];

    const int tid = threadIdx.x;
    const int ty  = tid >> 4;          // 0..15
    const int tx  = tid & 15;          // 0..15
    const int qb  = blockIdx.x;        // 0..31
    const int b   = blockIdx.y >> 4;
    const int h   = blockIdx.y & 15;

    const size_t base = (size_t)b * SEQ * DMODEL + (size_t)h * DK;
    const float* qp = q + base;
    const float* kp = k + base;
    const float* vp = v + base;
    float*       op = out + base;

    // Load Q tile (64 rows x 64 d)
#pragma unroll
    for (int it = 0; it < 4; it++) {
        int idx = tid + it * 256;          // 0..1023
        int r   = idx >> 4;                // 0..63
        int c   = (idx & 15) * 4;          // 0..60
        *(float4*)&Qs[r * APITCH + c] =
            *(const float4*)&qp[(size_t)(qb * 64 + r) * DMODEL + c];
    }
    if (tid < 64) { mrow[tid] = -1e30f; lrow[tid] = 0.f; }

    float acc[4][4];
#pragma unroll
    for (int i = 0; i < 4; i++)
#pragma unroll
        for (int j = 0; j < 4; j++) acc[i][j] = 0.f;

    __syncthreads();

    const float scale = 0.125f;            // 1/sqrt(64)

    for (int kb = 0; kb <= qb; kb++) {
        // Load K and V tiles
#pragma unroll
        for (int it = 0; it < 4; it++) {
            int idx = tid + it * 256;
            int r   = idx >> 4;
            int c   = (idx & 15) * 4;
            *(float4*)&Ks[r * APITCH + c] =
                *(const float4*)&kp[(size_t)(kb * 64 + r) * DMODEL + c];
            *(float4*)&Vs[r * APITCH + c] =
                *(const float4*)&vp[(size_t)(kb * 64 + r) * DMODEL + c];
        }
        __syncthreads();

        // Logits: L[r][c] = sum_d Q[r][d] * K[c][d]
        float lf[4][4];
#pragma unroll
        for (int i = 0; i < 4; i++)
#pragma unroll
            for (int j = 0; j < 4; j++) lf[i][j] = 0.f;

#pragma unroll 4
        for (int d = 0; d < DK; d++) {
            float aa[4], bb[4];
#pragma unroll
            for (int i = 0; i < 4; i++) aa[i] = Qs[(ty * 4 + i) * APITCH + d];
#pragma unroll
            for (int j = 0; j < 4; j++) bb[j] = Ks[(tx * 4 + j) * APITCH + d];
#pragma unroll
            for (int i = 0; i < 4; i++)
#pragma unroll
                for (int j = 0; j < 4; j++)
                    lf[i][j] = fmaf(aa[i], bb[j], lf[i][j]);
        }

        // Scale + causal mask + write to smem
        const bool diag = (kb == qb);
#pragma unroll
        for (int i = 0; i < 4; i++) {
            int gr = qb * 64 + ty * 4 + i;
#pragma unroll
            for (int j = 0; j < 4; j++) {
                int gc = kb * 64 + tx * 4 + j;
                float val = lf[i][j] * scale;
                if (diag && gc > gr) val = -1e30f;
                Ls[(ty * 4 + i) * APITCH + tx * 4 + j] = val;
            }
        }
        __syncthreads();

        // Streaming softmax update: one thread per q-row
        if (tid < 64) {
            int r = tid;
            float mold = mrow[r];
            float rmax = -1e30f;
#pragma unroll 8
            for (int c = 0; c < 64; c++)
                rmax = fmaxf(rmax, Ls[r * APITCH + c]);
            float mnew  = fmaxf(mold, rmax);
            float alpha = __expf(mold - mnew);
            float s = 0.f;
#pragma unroll 8
            for (int c = 0; c < 64; c++) {
                float p = __expf(Ls[r * APITCH + c] - mnew);
                Ls[r * APITCH + c] = p;
                s += p;
            }
            lrow[r] = lrow[r] * alpha + s;
            mrow[r] = mnew;
            arow[r] = alpha;
        }
        __syncthreads();

        // O = O*alpha + P @ V
#pragma unroll
        for (int i = 0; i < 4; i++) {
            float al = arow[ty * 4 + i];
#pragma unroll
            for (int j = 0; j < 4; j++) acc[i][j] *= al;
        }
#pragma unroll 4
        for (int c = 0; c < 64; c++) {
            float pv[4], vv[4];
#pragma unroll
            for (int i = 0; i < 4; i++) pv[i] = Ls[(ty * 4 + i) * APITCH + c];
#pragma unroll
            for (int j = 0; j < 4; j++) vv[j] = Vs[c * APITCH + tx * 4 + j];
#pragma unroll
            for (int i = 0; i < 4; i++)
#pragma unroll
                for (int j = 0; j < 4; j++)
                    acc[i][j] = fmaf(pv[i], vv[j], acc[i][j]);
        }
        __syncthreads();   // before next tile overwrites Ks/Vs/Ls
    }

    // Finalize: divide by l and store
#pragma unroll
    for (int i = 0; i < 4; i++) {
        float inv = 1.f / lrow[ty * 4 + i];
        size_t rowoff = (size_t)(qb * 64 + ty * 4 + i) * DMODEL;
#pragma unroll
        for (int j = 0; j < 4; j++)
            op[rowoff + tx * 4 + j] = acc[i][j] * inv;
    }
}

// ---------------------------------------------------------------------------
// Launch: 3 projections -> attention -> output projection
// ---------------------------------------------------------------------------
extern "C" void kernel_launch(void* const* d_in, const int* in_sizes, int n_in,
                              void* d_out, int out_size)
{
    const float* Q   = (const float*)d_in[0];
    const float* K   = (const float*)d_in[1];
    const float* V   = (const float*)d_in[2];
    // d_in[3] = mask (bool) — causal, known statically, unused
    const float* W_Q = (const float*)d_in[4];
    const float* W_K = (const float*)d_in[5];
    const float* W_V = (const float*)d_in[6];
    const float* W_O = (const float*)d_in[7];
    float* out = (float*)d_out;

    float *pq, *pk, *pv, *pa;
    cudaGetSymbolAddress((void**)&pq, g_q);
    cudaGetSymbolAddress((void**)&pk, g_k);
    cudaGetSymbolAddress((void**)&pv, g_v);
    cudaGetSymbolAddress((void**)&pa, g_attn);

    cudaFuncSetAttribute(attn_kernel,
                         cudaFuncAttributeMaxDynamicSharedMemorySize, ATTN_SMEM);

    dim3 gg(DMODEL / BN, ROWS / BM);   // (8, 32)

    gemm_nt<<<gg, 256>>>(Q, W_Q, pq, ROWS, DMODEL, DMODEL);
    gemm_nt<<<gg, 256>>>(K, W_K, pk, ROWS, DMODEL, DMODEL);
    gemm_nt<<<gg, 256>>>(V, W_V, pv, ROWS, DMODEL, DMODEL);

    attn_kernel<<<dim3(SEQ / 64, BATCH * HEADS), 256, ATTN_SMEM>>>(pq, pk, pv, pa);

    gemm_nt<<<gg, 256>>>(pa, W_O, out, ROWS, DMODEL, DMODEL);
}

// round 5
// speedup vs baseline: 1.2341x; 1.2341x over previous
#include <cuda_runtime.h>
#include <cuda_bf16.h>
#include <cstdint>

// Problem constants
#define BATCH   2
#define SEQ     2048
#define DMODEL  1024
#define HEADS   16
#define DK      64
#define ROWS    (BATCH * SEQ)          // 4096
#define K2      3072                   // split-bf16 concatenated K (3 * 1024)

// ---------------------------------------------------------------------------
// Scratch (device globals: allocation-free, graph-capture safe)
// ---------------------------------------------------------------------------
__device__ float g_q[ROWS * DMODEL];
__device__ float g_k[ROWS * DMODEL];
__device__ float g_v[ROWS * DMODEL];
__device__ float g_attn[ROWS * DMODEL];
__device__ __nv_bfloat16 g_asplit[(size_t)ROWS * K2];     // activations, split
__device__ __nv_bfloat16 g_wsplit[(size_t)DMODEL * K2];   // weights, split

// ---------------------------------------------------------------------------
// PTX helpers (sm_80+ features only: cp.async, ldmatrix, mma.sync)
// ---------------------------------------------------------------------------
__device__ __forceinline__ uint32_t smem_u32(const void* p) {
    uint32_t a;
    asm("{ .reg .u64 t; cvta.to.shared.u64 t, %1; cvt.u32.u64 %0, t; }"
        : "=r"(a) : "l"(p));
    return a;
}
__device__ __forceinline__ void cp16(uint32_t saddr, const void* g) {
    asm volatile("cp.async.cg.shared.global [%0], [%1], 16;"
                 :: "r"(saddr), "l"(g) : "memory");
}
__device__ __forceinline__ void cp_commit() {
    asm volatile("cp.async.commit_group;" ::: "memory");
}
__device__ __forceinline__ void cp_wait1() { asm volatile("cp.async.wait_group 1;" ::: "memory"); }
__device__ __forceinline__ void cp_wait0() { asm volatile("cp.async.wait_group 0;" ::: "memory"); }

__device__ __forceinline__ void ldmx4(uint32_t* r, uint32_t addr) {
    asm volatile("ldmatrix.sync.aligned.m8n8.x4.shared.b16 {%0,%1,%2,%3}, [%4];"
                 : "=r"(r[0]), "=r"(r[1]), "=r"(r[2]), "=r"(r[3]) : "r"(addr));
}
__device__ __forceinline__ void mma16816(float* d, const uint32_t* a, const uint32_t* b) {
    asm volatile(
        "mma.sync.aligned.m16n8k16.row.col.f32.bf16.bf16.f32 "
        "{%0,%1,%2,%3}, {%4,%5,%6,%7}, {%8,%9}, {%0,%1,%2,%3};"
        : "+f"(d[0]), "+f"(d[1]), "+f"(d[2]), "+f"(d[3])
        : "r"(a[0]), "r"(a[1]), "r"(a[2]), "r"(a[3]), "r"(b[0]), "r"(b[1]));
}

// ---------------------------------------------------------------------------
// Split-bf16 conversion: x fp32 [rows,1024] -> y bf16 [rows,3072]
// act pattern: [hi | lo | hi];  wgt pattern: [hi | hi | lo]
// ---------------------------------------------------------------------------
__global__ void split_kernel(const float4* __restrict__ x,
                             __nv_bfloat16* __restrict__ y, int act)
{
    size_t i = (size_t)blockIdx.x * blockDim.x + threadIdx.x;  // one float4 each
    size_t r  = i >> 8;            // 256 float4 per 1024-row
    size_t c  = (i & 255) * 4;
    float4 v = x[i];
    float f[4] = {v.x, v.y, v.z, v.w};
    __nv_bfloat16 h[4], l[4];
#pragma unroll
    for (int j = 0; j < 4; j++) {
        h[j] = __float2bfloat16(f[j]);
        l[j] = __float2bfloat16(f[j] - __bfloat162float(h[j]));
    }
    uint2 hv = *(uint2*)h;
    uint2 lv = *(uint2*)l;
    __nv_bfloat16* row = y + r * K2;
    *(uint2*)&row[c] = hv;
    if (act) {
        *(uint2*)&row[1024 + c] = lv;
        *(uint2*)&row[2048 + c] = hv;
    } else {
        *(uint2*)&row[1024 + c] = hv;
        *(uint2*)&row[2048 + c] = lv;
    }
}

// ---------------------------------------------------------------------------
// mma.sync bf16 NT GEMM: C[M,N] = A'[M,K2] @ B'[N,K2]^T, fp32 accumulate.
// Tile 128(M) x 256(N), BK=32, 512 threads (16 warps, 64x32 warp tiles),
// double-buffered cp.async, XOR-swizzled 64B smem rows, ldmatrix fragments.
// ---------------------------------------------------------------------------
#define GM 128
#define GN 256
#define BKE 32                  // K elems per chunk
#define CHUNKB 64               // bytes per smem row (32 bf16)
#define NCHUNK (K2 / BKE)       // 96

__global__ __launch_bounds__(512, 1)
void gemm_mma(const __nv_bfloat16* __restrict__ A, const __nv_bfloat16* __restrict__ B,
              float* __restrict__ C)
{
    __shared__ __align__(128) uint8_t smA[2][GM * CHUNKB];   // 2 x 8KB
    __shared__ __align__(128) uint8_t smB[2][GN * CHUNKB];   // 2 x 16KB

    const int tid    = threadIdx.x;
    const int wid    = tid >> 5;
    const int lane   = tid & 31;
    const int warp_m = wid >> 3;          // 0..1  -> m offset *64
    const int warp_n = wid & 7;           // 0..7  -> n offset *32
    const int rowBase = blockIdx.y * GM;
    const int colBase = blockIdx.x * GN;

    float acc[4][4][4];
#pragma unroll
    for (int i = 0; i < 4; i++)
#pragma unroll
        for (int j = 0; j < 4; j++)
#pragma unroll
            for (int t = 0; t < 4; t++) acc[i][j][t] = 0.f;

    // ldmatrix lane-dependent offsets
    const int a_moff = ((lane >> 3) & 1) * 8 + (lane & 7);   // row within 16-row frag
    const int a_half = lane >> 4;                            // k-half (0/1)
    const int b_noff = (lane >> 4) * 8 + (lane & 7);         // row within 16-row pair
    const int b_half = (lane >> 3) & 1;                      // k-half (0/1)

    auto load_chunk = [&](int chunk, int buf) {
        const int k0 = chunk * BKE;
        const uint32_t abase = smem_u32(&smA[buf][0]);
        const uint32_t bbase = smem_u32(&smB[buf][0]);
        // 1536 x 16B chunks total (A:512, B:1024); 3 per thread
#pragma unroll
        for (int it = 0; it < 3; it++) {
            int u = tid + it * 512;
            if (u < 512) {
                int r = u >> 2, c = u & 3;
                cp16(abase + r * CHUNKB + ((c ^ (r & 3)) * 16),
                     A + (size_t)(rowBase + r) * K2 + k0 + c * 8);
            } else {
                int v2 = u - 512;
                int r = v2 >> 2, c = v2 & 3;
                cp16(bbase + r * CHUNKB + ((c ^ (r & 3)) * 16),
                     B + (size_t)(colBase + r) * K2 + k0 + c * 8);
            }
        }
        cp_commit();
    };

    load_chunk(0, 0);
    load_chunk(1, 1);

    for (int i = 0; i < NCHUNK; i++) {
        const int cur = i & 1;
        if (i + 1 < NCHUNK) cp_wait1(); else cp_wait0();
        __syncthreads();

        const uint32_t abase = smem_u32(&smA[cur][0]);
        const uint32_t bbase = smem_u32(&smB[cur][0]);
#pragma unroll
        for (int ks = 0; ks < 2; ks++) {
            uint32_t afrag[4][4], bfrag[4][2];
#pragma unroll
            for (int fi = 0; fi < 4; fi++) {
                int m = warp_m * 64 + fi * 16 + a_moff;
                uint32_t addr = abase + m * CHUNKB
                              + (((ks * 2 + a_half) ^ (a_moff & 3)) * 16);
                ldmx4(afrag[fi], addr);
            }
#pragma unroll
            for (int jj = 0; jj < 2; jj++) {
                int n = warp_n * 32 + jj * 16 + b_noff;
                uint32_t addr = bbase + n * CHUNKB
                              + (((ks * 2 + b_half) ^ (b_noff & 3)) * 16);
                uint32_t r[4];
                ldmx4(r, addr);
                bfrag[jj * 2][0]     = r[0];
                bfrag[jj * 2][1]     = r[1];
                bfrag[jj * 2 + 1][0] = r[2];
                bfrag[jj * 2 + 1][1] = r[3];
            }
#pragma unroll
            for (int fi = 0; fi < 4; fi++)
#pragma unroll
                for (int fj = 0; fj < 4; fj++)
                    mma16816(acc[fi][fj], afrag[fi], bfrag[fj]);
        }
        __syncthreads();
        if (i + 2 < NCHUNK) load_chunk(i + 2, cur);
    }

    // Epilogue: fragment -> gmem (row-major C [*, DMODEL])
    const int erow = (lane >> 2);
    const int ecol = (lane & 3) * 2;
#pragma unroll
    for (int fi = 0; fi < 4; fi++) {
#pragma unroll
        for (int fj = 0; fj < 4; fj++) {
            int row = rowBase + warp_m * 64 + fi * 16 + erow;
            int col = colBase + warp_n * 32 + fj * 8 + ecol;
            *(float2*)&C[(size_t)row * DMODEL + col] =
                make_float2(acc[fi][fj][0], acc[fi][fj][1]);
            *(float2*)&C[(size_t)(row + 8) * DMODEL + col] =
                make_float2(acc[fi][fj][2], acc[fi][fj][3]);
        }
    }
}

// ---------------------------------------------------------------------------
// Causal flash attention (fp32 SIMT). 64x64 tiles, streaming softmax with
// 4 threads per row (shfl reduction).
// ---------------------------------------------------------------------------
#define APITCH 68
#define ATTN_SMEM (4 * 64 * APITCH * 4)

__global__ __launch_bounds__(256, 2)
void attn_kernel(const float* __restrict__ q, const float* __restrict__ k,
                 const float* __restrict__ v, float* __restrict__ out)
{
    extern __shared__ float sm[];
    float* Qs = sm;
    float* Ks = Qs + 64 * APITCH;
    float* Vs = Ks + 64 * APITCH;
    float* Ls = Vs + 64 * APITCH;

    __shared__ float mrow[64], lrow[64], arow[64];

    const int tid = threadIdx.x;
    const int ty  = tid >> 4;
    const int tx  = tid & 15;
    const int qb  = blockIdx.x;
    const int b   = blockIdx.y >> 4;
    const int h   = blockIdx.y & 15;

    const size_t base = (size_t)b * SEQ * DMODEL + (size_t)h * DK;
    const float* qp = q + base;
    const float* kp = k + base;
    const float* vp = v + base;
    float*       op = out + base;

#pragma unroll
    for (int it = 0; it < 4; it++) {
        int idx = tid + it * 256;
        int r   = idx >> 4;
        int c   = (idx & 15) * 4;
        *(float4*)&Qs[r * APITCH + c] =
            *(const float4*)&qp[(size_t)(qb * 64 + r) * DMODEL + c];
    }
    if (tid < 64) { mrow[tid] = -1e30f; lrow[tid] = 0.f; }

    float acc[4][4];
#pragma unroll
    for (int i = 0; i < 4; i++)
#pragma unroll
        for (int j = 0; j < 4; j++) acc[i][j] = 0.f;

    __syncthreads();

    const float scale = 0.125f;

    for (int kb = 0; kb <= qb; kb++) {
#pragma unroll
        for (int it = 0; it < 4; it++) {
            int idx = tid + it * 256;
            int r   = idx >> 4;
            int c   = (idx & 15) * 4;
            *(float4*)&Ks[r * APITCH + c] =
                *(const float4*)&kp[(size_t)(kb * 64 + r) * DMODEL + c];
            *(float4*)&Vs[r * APITCH + c] =
                *(const float4*)&vp[(size_t)(kb * 64 + r) * DMODEL + c];
        }
        __syncthreads();

        float lf[4][4];
#pragma unroll
        for (int i = 0; i < 4; i++)
#pragma unroll
            for (int j = 0; j < 4; j++) lf[i][j] = 0.f;

#pragma unroll 4
        for (int d = 0; d < DK; d++) {
            float aa[4], bb[4];
#pragma unroll
            for (int i = 0; i < 4; i++) aa[i] = Qs[(ty * 4 + i) * APITCH + d];
#pragma unroll
            for (int j = 0; j < 4; j++) bb[j] = Ks[(tx * 4 + j) * APITCH + d];
#pragma unroll
            for (int i = 0; i < 4; i++)
#pragma unroll
                for (int j = 0; j < 4; j++)
                    lf[i][j] = fmaf(aa[i], bb[j], lf[i][j]);
        }

        const bool diag = (kb == qb);
#pragma unroll
        for (int i = 0; i < 4; i++) {
            int gr = qb * 64 + ty * 4 + i;
#pragma unroll
            for (int j = 0; j < 4; j++) {
                int gc = kb * 64 + tx * 4 + j;
                float val = lf[i][j] * scale;
                if (diag && gc > gr) val = -1e30f;
                Ls[(ty * 4 + i) * APITCH + tx * 4 + j] = val;
            }
        }
        __syncthreads();

        // Streaming softmax: 4 threads per q-row, 16 cols each
        {
            const int r   = tid >> 2;
            const int sub = tid & 3;
            float mold = mrow[r];
            float rmax = -1e30f;
#pragma unroll
            for (int c = 0; c < 16; c++)
                rmax = fmaxf(rmax, Ls[r * APITCH + sub * 16 + c]);
            rmax = fmaxf(rmax, __shfl_xor_sync(0xFFFFFFFF, rmax, 1));
            rmax = fmaxf(rmax, __shfl_xor_sync(0xFFFFFFFF, rmax, 2));
            float mnew  = fmaxf(mold, rmax);
            float alpha = __expf(mold - mnew);
            float s = 0.f;
#pragma unroll
            for (int c = 0; c < 16; c++) {
                float p = __expf(Ls[r * APITCH + sub * 16 + c] - mnew);
                Ls[r * APITCH + sub * 16 + c] = p;
                s += p;
            }
            s += __shfl_xor_sync(0xFFFFFFFF, s, 1);
            s += __shfl_xor_sync(0xFFFFFFFF, s, 2);
            if (sub == 0) {
                lrow[r] = lrow[r] * alpha + s;
                mrow[r] = mnew;
                arow[r] = alpha;
            }
        }
        __syncthreads();

#pragma unroll
        for (int i = 0; i < 4; i++) {
            float al = arow[ty * 4 + i];
#pragma unroll
            for (int j = 0; j < 4; j++) acc[i][j] *= al;
        }
#pragma unroll 4
        for (int c = 0; c < 64; c++) {
            float pv[4], vv[4];
#pragma unroll
            for (int i = 0; i < 4; i++) pv[i] = Ls[(ty * 4 + i) * APITCH + c];
#pragma unroll
            for (int j = 0; j < 4; j++) vv[j] = Vs[c * APITCH + tx * 4 + j];
#pragma unroll
            for (int i = 0; i < 4; i++)
#pragma unroll
                for (int j = 0; j < 4; j++)
                    acc[i][j] = fmaf(pv[i], vv[j], acc[i][j]);
        }
        __syncthreads();
    }

#pragma unroll
    for (int i = 0; i < 4; i++) {
        float inv = 1.f / lrow[ty * 4 + i];
        size_t rowoff = (size_t)(qb * 64 + ty * 4 + i) * DMODEL;
#pragma unroll
        for (int j = 0; j < 4; j++)
            op[rowoff + tx * 4 + j] = acc[i][j] * inv;
    }
}

// ---------------------------------------------------------------------------
// Launch
// ---------------------------------------------------------------------------
extern "C" void kernel_launch(void* const* d_in, const int* in_sizes, int n_in,
                              void* d_out, int out_size)
{
    const float* Q   = (const float*)d_in[0];
    const float* K   = (const float*)d_in[1];
    const float* V   = (const float*)d_in[2];
    const float* W_Q = (const float*)d_in[4];
    const float* W_K = (const float*)d_in[5];
    const float* W_V = (const float*)d_in[6];
    const float* W_O = (const float*)d_in[7];
    float* out = (float*)d_out;

    float *pq, *pk, *pv, *pa;
    __nv_bfloat16 *pas, *pws;
    cudaGetSymbolAddress((void**)&pq, g_q);
    cudaGetSymbolAddress((void**)&pk, g_k);
    cudaGetSymbolAddress((void**)&pv, g_v);
    cudaGetSymbolAddress((void**)&pa, g_attn);
    cudaGetSymbolAddress((void**)&pas, g_asplit);
    cudaGetSymbolAddress((void**)&pws, g_wsplit);

    cudaFuncSetAttribute(attn_kernel,
                         cudaFuncAttributeMaxDynamicSharedMemorySize, ATTN_SMEM);

    const int actBlocks = ROWS * DMODEL / 4 / 256;     // 4096
    const int wgtBlocks = DMODEL * DMODEL / 4 / 256;   // 1024
    dim3 gg(DMODEL / GN, ROWS / GM);                   // (4, 32)

    // Q projection
    split_kernel<<<actBlocks, 256>>>((const float4*)Q, pas, 1);
    split_kernel<<<wgtBlocks, 256>>>((const float4*)W_Q, pws, 0);
    gemm_mma<<<gg, 512>>>(pas, pws, pq);
    // K projection
    split_kernel<<<actBlocks, 256>>>((const float4*)K, pas, 1);
    split_kernel<<<wgtBlocks, 256>>>((const float4*)W_K, pws, 0);
    gemm_mma<<<gg, 512>>>(pas, pws, pk);
    // V projection
    split_kernel<<<actBlocks, 256>>>((const float4*)V, pas, 1);
    split_kernel<<<wgtBlocks, 256>>>((const float4*)W_V, pws, 0);
    gemm_mma<<<gg, 512>>>(pas, pws, pv);

    // Attention
    attn_kernel<<<dim3(SEQ / 64, BATCH * HEADS), 256, ATTN_SMEM>>>(pq, pk, pv, pa);

    // Output projection
    split_kernel<<<actBlocks, 256>>>((const float4*)pa, pas, 1);
    split_kernel<<<wgtBlocks, 256>>>((const float4*)W_O, pws, 0);
    gemm_mma<<<gg, 512>>>(pas, pws, out);
}

// round 7
// speedup vs baseline: 2.2024x; 1.7846x over previous
#include <cuda_runtime.h>
#include <cuda_bf16.h>
#include <cstdint>

// Problem constants
#define BATCH   2
#define SEQ     2048
#define DMODEL  1024
#define HEADS   16
#define DK      64
#define ROWS    (BATCH * SEQ)          // 4096
#define K2      3072                   // split-bf16 concatenated K (3 * 1024)

// ---------------------------------------------------------------------------
// Scratch (device globals: allocation-free, graph-capture safe)
// ---------------------------------------------------------------------------
__device__ float g_q[ROWS * DMODEL];
__device__ float g_k[ROWS * DMODEL];
__device__ float g_v[ROWS * DMODEL];
__device__ float g_attn[ROWS * DMODEL];
__device__ __nv_bfloat16 g_asplit[(size_t)ROWS * K2];     // activations, split
__device__ __nv_bfloat16 g_wsplit[(size_t)DMODEL * K2];   // weights, split
// attention operands (pre-split, per-head layouts)
__device__ __nv_bfloat16 g_qs[(size_t)32 * SEQ * 192];    // [bh][s][192]  [hi|lo|hi]
__device__ __nv_bfloat16 g_ks[(size_t)32 * SEQ * 192];    // [bh][s][192]  [hi|hi|lo]
__device__ __nv_bfloat16 g_vth[(size_t)32 * DK * SEQ];    // [bh][d][s]    V^T hi
__device__ __nv_bfloat16 g_vtl[(size_t)32 * DK * SEQ];    // [bh][d][s]    V^T lo

// ---------------------------------------------------------------------------
// PTX helpers (sm_80+ features only: cp.async, ldmatrix, mma.sync)
// ---------------------------------------------------------------------------
__device__ __forceinline__ uint32_t smem_u32(const void* p) {
    uint32_t a;
    asm("{ .reg .u64 t; cvta.to.shared.u64 t, %1; cvt.u32.u64 %0, t; }"
        : "=r"(a) : "l"(p));
    return a;
}
__device__ __forceinline__ void cp16(uint32_t saddr, const void* g) {
    asm volatile("cp.async.cg.shared.global [%0], [%1], 16;"
                 :: "r"(saddr), "l"(g) : "memory");
}
__device__ __forceinline__ void cp_commit() {
    asm volatile("cp.async.commit_group;" ::: "memory");
}
__device__ __forceinline__ void cp_wait1() { asm volatile("cp.async.wait_group 1;" ::: "memory"); }
__device__ __forceinline__ void cp_wait0() { asm volatile("cp.async.wait_group 0;" ::: "memory"); }

__device__ __forceinline__ void ldmx4(uint32_t* r, uint32_t addr) {
    asm volatile("ldmatrix.sync.aligned.m8n8.x4.shared.b16 {%0,%1,%2,%3}, [%4];"
                 : "=r"(r[0]), "=r"(r[1]), "=r"(r[2]), "=r"(r[3]) : "r"(addr));
}
__device__ __forceinline__ void mma16816(float* d, const uint32_t* a, const uint32_t* b) {
    asm volatile(
        "mma.sync.aligned.m16n8k16.row.col.f32.bf16.bf16.f32 "
        "{%0,%1,%2,%3}, {%4,%5,%6,%7}, {%8,%9}, {%0,%1,%2,%3};"
        : "+f"(d[0]), "+f"(d[1]), "+f"(d[2]), "+f"(d[3])
        : "r"(a[0]), "r"(a[1]), "r"(a[2]), "r"(a[3]), "r"(b[0]), "r"(b[1]));
}

// ---------------------------------------------------------------------------
// Split-bf16 conversion for projection GEMMs: fp32 [rows,1024] -> bf16 [rows,3072]
// act pattern: [hi | lo | hi];  wgt pattern: [hi | hi | lo]
// ---------------------------------------------------------------------------
__global__ void split_kernel(const float4* __restrict__ x,
                             __nv_bfloat16* __restrict__ y, int act)
{
    size_t i = (size_t)blockIdx.x * blockDim.x + threadIdx.x;
    size_t r  = i >> 8;
    size_t c  = (i & 255) * 4;
    float4 v = x[i];
    float f[4] = {v.x, v.y, v.z, v.w};
    __nv_bfloat16 h[4], l[4];
#pragma unroll
    for (int j = 0; j < 4; j++) {
        h[j] = __float2bfloat16(f[j]);
        l[j] = __float2bfloat16(f[j] - __bfloat162float(h[j]));
    }
    uint2 hv = *(uint2*)h;
    uint2 lv = *(uint2*)l;
    __nv_bfloat16* row = y + r * K2;
    *(uint2*)&row[c] = hv;
    if (act) {
        *(uint2*)&row[1024 + c] = lv;
        *(uint2*)&row[2048 + c] = hv;
    } else {
        *(uint2*)&row[1024 + c] = hv;
        *(uint2*)&row[2048 + c] = lv;
    }
}

// ---------------------------------------------------------------------------
// Q/K split for attention: g_q/g_k fp32 [4096,1024] -> [bh][s][192]
// pat 0 (Q): [hi|lo|hi] (scale folded in);  pat 1 (K): [hi|hi|lo]
// ---------------------------------------------------------------------------
__global__ void qk_split(const float* __restrict__ x, __nv_bfloat16* __restrict__ y,
                         float scale, int pat)
{
    int idx = blockIdx.x * blockDim.x + threadIdx.x;   // pair index (2M)
    int row = idx >> 9;                                // global row (b*2048+s)
    int d2  = (idx & 511) * 2;
    int h   = d2 >> 6;
    int d   = d2 & 63;
    float f0 = x[(size_t)row * 1024 + d2]     * scale;
    float f1 = x[(size_t)row * 1024 + d2 + 1] * scale;
    __nv_bfloat16 h0 = __float2bfloat16(f0), h1 = __float2bfloat16(f1);
    float l0f = f0 - __bfloat162float(h0), l1f = f1 - __bfloat162float(h1);
    __nv_bfloat162 hp = __nv_bfloat162(h0, h1);
    __nv_bfloat162 lp = __nv_bfloat162(__float2bfloat16(l0f), __float2bfloat16(l1f));
    int b = row >> 11, s = row & 2047;
    __nv_bfloat16* dst = y + (((size_t)(b * 16 + h) * SEQ) + s) * 192;
    *(__nv_bfloat162*)(dst + d) = hp;
    if (pat == 0) {
        *(__nv_bfloat162*)(dst + 64 + d)  = lp;
        *(__nv_bfloat162*)(dst + 128 + d) = hp;
    } else {
        *(__nv_bfloat162*)(dst + 64 + d)  = hp;
        *(__nv_bfloat162*)(dst + 128 + d) = lp;
    }
}

// ---------------------------------------------------------------------------
// V transpose+split: g_v fp32 [4096,1024] -> vth/vtl [bh][64][2048]
// ---------------------------------------------------------------------------
__global__ void vt_split(const float* __restrict__ v,
                         __nv_bfloat16* __restrict__ vh, __nv_bfloat16* __restrict__ vl)
{
    __shared__ float t[64][65];
    const int bh = blockIdx.x;        // 32
    const int st = blockIdx.y;        // 32 s-tiles
    const int b = bh >> 4, h = bh & 15;
    const int tid = threadIdx.x;      // 256
    for (int i = tid; i < 64 * 16; i += 256) {
        int r = i >> 4, c4 = (i & 15) * 4;
        float4 val = *(const float4*)&v[((size_t)(b * SEQ + st * 64 + r)) * 1024 + h * 64 + c4];
        t[r][c4] = val.x; t[r][c4 + 1] = val.y; t[r][c4 + 2] = val.z; t[r][c4 + 3] = val.w;
    }
    __syncthreads();
    for (int i = tid; i < 64 * 32; i += 256) {
        int d = i >> 5, sp = (i & 31) * 2;
        float f0 = t[sp][d], f1 = t[sp + 1][d];
        __nv_bfloat16 h0 = __float2bfloat16(f0), h1 = __float2bfloat16(f1);
        __nv_bfloat162 hp = __nv_bfloat162(h0, h1);
        __nv_bfloat162 lp = __nv_bfloat162(
            __float2bfloat16(f0 - __bfloat162float(h0)),
            __float2bfloat16(f1 - __bfloat162float(h1)));
        size_t off = ((size_t)bh * 64 + d) * SEQ + st * 64 + sp;
        *(__nv_bfloat162*)(vh + off) = hp;
        *(__nv_bfloat162*)(vl + off) = lp;
    }
}

// ---------------------------------------------------------------------------
// mma.sync bf16 NT GEMM (projections) — unchanged from R5 (validated).
// ---------------------------------------------------------------------------
#define GM 128
#define GN 256
#define BKE 32
#define CHUNKB 64
#define NCHUNK (K2 / BKE)

__global__ __launch_bounds__(512, 1)
void gemm_mma(const __nv_bfloat16* __restrict__ A, const __nv_bfloat16* __restrict__ B,
              float* __restrict__ C)
{
    __shared__ __align__(128) uint8_t smA[2][GM * CHUNKB];
    __shared__ __align__(128) uint8_t smB[2][GN * CHUNKB];

    const int tid    = threadIdx.x;
    const int wid    = tid >> 5;
    const int lane   = tid & 31;
    const int warp_m = wid >> 3;
    const int warp_n = wid & 7;
    const int rowBase = blockIdx.y * GM;
    const int colBase = blockIdx.x * GN;

    float acc[4][4][4];
#pragma unroll
    for (int i = 0; i < 4; i++)
#pragma unroll
        for (int j = 0; j < 4; j++)
#pragma unroll
            for (int t = 0; t < 4; t++) acc[i][j][t] = 0.f;

    const int a_moff = ((lane >> 3) & 1) * 8 + (lane & 7);
    const int a_half = lane >> 4;
    const int b_noff = (lane >> 4) * 8 + (lane & 7);
    const int b_half = (lane >> 3) & 1;

    auto load_chunk = [&](int chunk, int buf) {
        const int k0 = chunk * BKE;
        const uint32_t abase = smem_u32(&smA[buf][0]);
        const uint32_t bbase = smem_u32(&smB[buf][0]);
#pragma unroll
        for (int it = 0; it < 3; it++) {
            int u = tid + it * 512;
            if (u < 512) {
                int r = u >> 2, c = u & 3;
                cp16(abase + r * CHUNKB + ((c ^ (r & 3)) * 16),
                     A + (size_t)(rowBase + r) * K2 + k0 + c * 8);
            } else {
                int v2 = u - 512;
                int r = v2 >> 2, c = v2 & 3;
                cp16(bbase + r * CHUNKB + ((c ^ (r & 3)) * 16),
                     B + (size_t)(colBase + r) * K2 + k0 + c * 8);
            }
        }
        cp_commit();
    };

    load_chunk(0, 0);
    load_chunk(1, 1);

    for (int i = 0; i < NCHUNK; i++) {
        const int cur = i & 1;
        if (i + 1 < NCHUNK) cp_wait1(); else cp_wait0();
        __syncthreads();

        const uint32_t abase = smem_u32(&smA[cur][0]);
        const uint32_t bbase = smem_u32(&smB[cur][0]);
#pragma unroll
        for (int ks = 0; ks < 2; ks++) {
            uint32_t afrag[4][4], bfrag[4][2];
#pragma unroll
            for (int fi = 0; fi < 4; fi++) {
                int m = warp_m * 64 + fi * 16 + a_moff;
                uint32_t addr = abase + m * CHUNKB
                              + (((ks * 2 + a_half) ^ (a_moff & 3)) * 16);
                ldmx4(afrag[fi], addr);
            }
#pragma unroll
            for (int jj = 0; jj < 2; jj++) {
                int n = warp_n * 32 + jj * 16 + b_noff;
                uint32_t addr = bbase + n * CHUNKB
                              + (((ks * 2 + b_half) ^ (b_noff & 3)) * 16);
                uint32_t r[4];
                ldmx4(r, addr);
                bfrag[jj * 2][0]     = r[0];
                bfrag[jj * 2][1]     = r[1];
                bfrag[jj * 2 + 1][0] = r[2];
                bfrag[jj * 2 + 1][1] = r[3];
            }
#pragma unroll
            for (int fi = 0; fi < 4; fi++)
#pragma unroll
                for (int fj = 0; fj < 4; fj++)
                    mma16816(acc[fi][fj], afrag[fi], bfrag[fj]);
        }
        __syncthreads();
        if (i + 2 < NCHUNK) load_chunk(i + 2, cur);
    }

    const int erow = (lane >> 2);
    const int ecol = (lane & 3) * 2;
#pragma unroll
    for (int fi = 0; fi < 4; fi++) {
#pragma unroll
        for (int fj = 0; fj < 4; fj++) {
            int row = rowBase + warp_m * 64 + fi * 16 + erow;
            int col = colBase + warp_n * 32 + fj * 8 + ecol;
            *(float2*)&C[(size_t)row * DMODEL + col] =
                make_float2(acc[fi][fj][0], acc[fi][fj][1]);
            *(float2*)&C[(size_t)(row + 8) * DMODEL + col] =
                make_float2(acc[fi][fj][2], acc[fi][fj][3]);
        }
    }
}

// ---------------------------------------------------------------------------
// Tensor-core causal flash attention.
// CTA: 256 threads = warp grid 4(m) x 2(n) over a 64x64 tile.
// Q'/K'/P' tiles: [64 rows][192 + pad] bf16, pitch 400B (conflict-free ldmatrix).
// VT' tile: [64 d][192] = [Vhi|Vhi|Vlo].  QK and PV both K'=192 (12 k16 steps).
// ---------------------------------------------------------------------------
#define APITCHB 400                   // bytes per smem row
#define TILEB   (64 * APITCHB)        // 25600
#define SQ_OFF  0
#define SK_OFF  TILEB
#define SV_OFF  (2 * TILEB)
#define SP_OFF  (3 * TILEB)
#define SST_OFF (4 * TILEB)           // state floats
#define ATTN_SMEM (SST_OFF + 512 * 4) // 104448

__global__ __launch_bounds__(256, 2)
void attn_mma(const __nv_bfloat16* __restrict__ qs, const __nv_bfloat16* __restrict__ ks,
              const __nv_bfloat16* __restrict__ vth, const __nv_bfloat16* __restrict__ vtl,
              float* __restrict__ out)
{
    extern __shared__ char sm[];
    const uint32_t sb = smem_u32(sm);
    float* st   = (float*)(sm + SST_OFF);
    float* mrow = st;            // [64]
    float* lrow = st + 64;       // [64]
    float* arow = st + 128;      // [64]
    float* mnew = st + 192;      // [64]
    float* pmax = st + 256;      // [2][64]
    float* psum = st + 384;      // [2][64]

    const int tid  = threadIdx.x;
    const int wid  = tid >> 5;
    const int lane = tid & 31;
    const int wm   = wid & 3;          // 16-row strip
    const int wn   = wid >> 2;         // 32-col strip
    const int qb   = blockIdx.x;
    const int bh   = blockIdx.y;

    const __nv_bfloat16* qsrc = qs  + ((size_t)bh * SEQ + qb * 64) * 192;
    const __nv_bfloat16* ksrc = ks  + (size_t)bh * SEQ * 192;
    const __nv_bfloat16* vhs  = vth + (size_t)bh * 64 * SEQ;
    const __nv_bfloat16* vls  = vtl + (size_t)bh * 64 * SEQ;

    // Q' load (once)
    for (int u = tid; u < 1536; u += 256) {
        int r = u / 24, c = u % 24;
        cp16(sb + SQ_OFF + r * APITCHB + c * 16, qsrc + (size_t)r * 192 + c * 8);
    }
    cp_commit();

    if (tid < 64) { mrow[tid] = -1e30f; lrow[tid] = 0.f; }

    float acco[4][4];
#pragma unroll
    for (int j = 0; j < 4; j++)
#pragma unroll
        for (int t = 0; t < 4; t++) acco[j][t] = 0.f;

    const int a_moff = ((lane >> 3) & 1) * 8 + (lane & 7);
    const int a_half = lane >> 4;
    const int b_noff = (lane >> 4) * 8 + (lane & 7);
    const int b_half = (lane >> 3) & 1;
    const int erow   = lane >> 2;
    const int ecol   = (lane & 3) * 2;
    const int r0 = wm * 16 + erow, r1 = r0 + 8;

    for (int kb = 0; kb <= qb; kb++) {
        // K' tile
        for (int u = tid; u < 1536; u += 256) {
            int r = u / 24, c = u % 24;
            cp16(sb + SK_OFF + r * APITCHB + c * 16,
                 ksrc + ((size_t)(kb * 64 + r)) * 192 + c * 8);
        }
        // VT' tile: cols [0:16) chunks from hi (dup), [16:24) from lo
        for (int u = tid; u < 1536; u += 256) {
            int r = u / 24, c = u % 24;
            const __nv_bfloat16* src = (c < 16)
                ? (vhs + (size_t)r * SEQ + kb * 64 + (c & 7) * 8)
                : (vls + (size_t)r * SEQ + kb * 64 + (c - 16) * 8);
            cp16(sb + SV_OFF + r * APITCHB + c * 16, src);
        }
        cp_commit();
        cp_wait0();
        __syncthreads();

        // ---- S = Q' K'^T  (12 k-steps) ----
        float accs[4][4];
#pragma unroll
        for (int j = 0; j < 4; j++)
#pragma unroll
            for (int t = 0; t < 4; t++) accs[j][t] = 0.f;

#pragma unroll
        for (int ks_ = 0; ks_ < 12; ks_++) {
            uint32_t af[4], bf[4][2];
            ldmx4(af, sb + SQ_OFF + (wm * 16 + a_moff) * APITCHB + ks_ * 32 + a_half * 16);
#pragma unroll
            for (int jj = 0; jj < 2; jj++) {
                uint32_t r[4];
                ldmx4(r, sb + SK_OFF + (wn * 32 + jj * 16 + b_noff) * APITCHB
                         + ks_ * 32 + b_half * 16);
                bf[jj * 2][0] = r[0]; bf[jj * 2][1] = r[1];
                bf[jj * 2 + 1][0] = r[2]; bf[jj * 2 + 1][1] = r[3];
            }
#pragma unroll
            for (int fj = 0; fj < 4; fj++) mma16816(accs[fj], af, bf[fj]);
        }

        // causal mask (diagonal tile)
        if (kb == qb) {
#pragma unroll
            for (int fj = 0; fj < 4; fj++) {
                int gc = wn * 32 + fj * 8 + ecol;
                if (gc     > r0) accs[fj][0] = -1e30f;
                if (gc + 1 > r0) accs[fj][1] = -1e30f;
                if (gc     > r1) accs[fj][2] = -1e30f;
                if (gc + 1 > r1) accs[fj][3] = -1e30f;
            }
        }

        // ---- row maxes ----
        float lm0 = -1e30f, lm1 = -1e30f;
#pragma unroll
        for (int fj = 0; fj < 4; fj++) {
            lm0 = fmaxf(lm0, fmaxf(accs[fj][0], accs[fj][1]));
            lm1 = fmaxf(lm1, fmaxf(accs[fj][2], accs[fj][3]));
        }
        lm0 = fmaxf(lm0, __shfl_xor_sync(0xFFFFFFFF, lm0, 1));
        lm0 = fmaxf(lm0, __shfl_xor_sync(0xFFFFFFFF, lm0, 2));
        lm1 = fmaxf(lm1, __shfl_xor_sync(0xFFFFFFFF, lm1, 1));
        lm1 = fmaxf(lm1, __shfl_xor_sync(0xFFFFFFFF, lm1, 2));
        if ((lane & 3) == 0) {
            pmax[wn * 64 + r0] = lm0;
            pmax[wn * 64 + r1] = lm1;
        }
        __syncthreads();

        if (tid < 64) {
            float mo = mrow[tid];
            float mn = fmaxf(mo, fmaxf(pmax[tid], pmax[64 + tid]));
            mnew[tid] = mn;
            arow[tid] = __expf(mo - mn);
            mrow[tid] = mn;
        }
        __syncthreads();

        // ---- exp, write P' (hi|lo|hi), partial sums, rescale O ----
        const float mn0 = mnew[r0], mn1 = mnew[r1];
        const float al0 = arow[r0], al1 = arow[r1];
        float s0 = 0.f, s1 = 0.f;
#pragma unroll
        for (int fj = 0; fj < 4; fj++) {
            int kc = wn * 32 + fj * 8 + ecol;
            float p00 = __expf(accs[fj][0] - mn0);
            float p01 = __expf(accs[fj][1] - mn0);
            float p10 = __expf(accs[fj][2] - mn1);
            float p11 = __expf(accs[fj][3] - mn1);
            s0 += p00 + p01;
            s1 += p10 + p11;
            __nv_bfloat16 h00 = __float2bfloat16(p00), h01 = __float2bfloat16(p01);
            __nv_bfloat16 h10 = __float2bfloat16(p10), h11 = __float2bfloat16(p11);
            __nv_bfloat162 hp0 = __nv_bfloat162(h00, h01);
            __nv_bfloat162 hp1 = __nv_bfloat162(h10, h11);
            __nv_bfloat162 lp0 = __nv_bfloat162(
                __float2bfloat16(p00 - __bfloat162float(h00)),
                __float2bfloat16(p01 - __bfloat162float(h01)));
            __nv_bfloat162 lp1 = __nv_bfloat162(
                __float2bfloat16(p10 - __bfloat162float(h10)),
                __float2bfloat16(p11 - __bfloat162float(h11)));
            char* pr0 = sm + SP_OFF + r0 * APITCHB;
            char* pr1 = sm + SP_OFF + r1 * APITCHB;
            *(__nv_bfloat162*)(pr0 + kc * 2)       = hp0;
            *(__nv_bfloat162*)(pr0 + 128 + kc * 2) = lp0;
            *(__nv_bfloat162*)(pr0 + 256 + kc * 2) = hp0;
            *(__nv_bfloat162*)(pr1 + kc * 2)       = hp1;
            *(__nv_bfloat162*)(pr1 + 128 + kc * 2) = lp1;
            *(__nv_bfloat162*)(pr1 + 256 + kc * 2) = hp1;
        }
        s0 += __shfl_xor_sync(0xFFFFFFFF, s0, 1);
        s0 += __shfl_xor_sync(0xFFFFFFFF, s0, 2);
        s1 += __shfl_xor_sync(0xFFFFFFFF, s1, 1);
        s1 += __shfl_xor_sync(0xFFFFFFFF, s1, 2);
        if ((lane & 3) == 0) {
            psum[wn * 64 + r0] = s0;
            psum[wn * 64 + r1] = s1;
        }
#pragma unroll
        for (int fj = 0; fj < 4; fj++) {
            acco[fj][0] *= al0; acco[fj][1] *= al0;
            acco[fj][2] *= al1; acco[fj][3] *= al1;
        }
        __syncthreads();
        if (tid < 64)
            lrow[tid] = lrow[tid] * arow[tid] + psum[tid] + psum[64 + tid];

        // ---- O += P' VT'^T  (12 k-steps) ----
#pragma unroll
        for (int ks_ = 0; ks_ < 12; ks_++) {
            uint32_t af[4], bf[4][2];
            ldmx4(af, sb + SP_OFF + (wm * 16 + a_moff) * APITCHB + ks_ * 32 + a_half * 16);
#pragma unroll
            for (int jj = 0; jj < 2; jj++) {
                uint32_t r[4];
                ldmx4(r, sb + SV_OFF + (wn * 32 + jj * 16 + b_noff) * APITCHB
                         + ks_ * 32 + b_half * 16);
                bf[jj * 2][0] = r[0]; bf[jj * 2][1] = r[1];
                bf[jj * 2 + 1][0] = r[2]; bf[jj * 2 + 1][1] = r[3];
            }
#pragma unroll
            for (int fj = 0; fj < 4; fj++) mma16816(acco[fj], af, bf[fj]);
        }
        __syncthreads();
    }

    // ---- finalize: O /= l, write [b, qb*64+q, h*64+d] ----
    const int b = bh >> 4, h = bh & 15;
    const float il0 = 1.f / lrow[r0];
    const float il1 = 1.f / lrow[r1];
    const size_t grow0 = (size_t)(b * SEQ + qb * 64 + r0) * DMODEL;
    const size_t grow1 = (size_t)(b * SEQ + qb * 64 + r1) * DMODEL;
#pragma unroll
    for (int fj = 0; fj < 4; fj++) {
        int col = h * 64 + wn * 32 + fj * 8 + ecol;
        *(float2*)&out[grow0 + col] = make_float2(acco[fj][0] * il0, acco[fj][1] * il0);
        *(float2*)&out[grow1 + col] = make_float2(acco[fj][2] * il1, acco[fj][3] * il1);
    }
}

// ---------------------------------------------------------------------------
// Launch
// ---------------------------------------------------------------------------
extern "C" void kernel_launch(void* const* d_in, const int* in_sizes, int n_in,
                              void* d_out, int out_size)
{
    const float* Q   = (const float*)d_in[0];
    const float* K   = (const float*)d_in[1];
    const float* V   = (const float*)d_in[2];
    const float* W_Q = (const float*)d_in[4];
    const float* W_K = (const float*)d_in[5];
    const float* W_V = (const float*)d_in[6];
    const float* W_O = (const float*)d_in[7];
    float* out = (float*)d_out;

    float *pq, *pk, *pv, *pa;
    __nv_bfloat16 *pas, *pws, *pqs, *pks, *pvh, *pvl;
    cudaGetSymbolAddress((void**)&pq, g_q);
    cudaGetSymbolAddress((void**)&pk, g_k);
    cudaGetSymbolAddress((void**)&pv, g_v);
    cudaGetSymbolAddress((void**)&pa, g_attn);
    cudaGetSymbolAddress((void**)&pas, g_asplit);
    cudaGetSymbolAddress((void**)&pws, g_wsplit);
    cudaGetSymbolAddress((void**)&pqs, g_qs);
    cudaGetSymbolAddress((void**)&pks, g_ks);
    cudaGetSymbolAddress((void**)&pvh, g_vth);
    cudaGetSymbolAddress((void**)&pvl, g_vtl);

    cudaFuncSetAttribute(attn_mma,
                         cudaFuncAttributeMaxDynamicSharedMemorySize, ATTN_SMEM);

    const int actBlocks = ROWS * DMODEL / 4 / 256;     // 4096
    const int wgtBlocks = DMODEL * DMODEL / 4 / 256;   // 1024
    const int qkBlocks  = ROWS * DMODEL / 2 / 256;     // 8192
    dim3 gg(DMODEL / GN, ROWS / GM);                   // (4, 32)

    // Projections
    split_kernel<<<actBlocks, 256>>>((const float4*)Q, pas, 1);
    split_kernel<<<wgtBlocks, 256>>>((const float4*)W_Q, pws, 0);
    gemm_mma<<<gg, 512>>>(pas, pws, pq);
    split_kernel<<<actBlocks, 256>>>((const float4*)K, pas, 1);
    split_kernel<<<wgtBlocks, 256>>>((const float4*)W_K, pws, 0);
    gemm_mma<<<gg, 512>>>(pas, pws, pk);
    split_kernel<<<actBlocks, 256>>>((const float4*)V, pas, 1);
    split_kernel<<<wgtBlocks, 256>>>((const float4*)W_V, pws, 0);
    gemm_mma<<<gg, 512>>>(pas, pws, pv);

    // Attention operand prep
    qk_split<<<qkBlocks, 256>>>(pq, pqs, 0.125f, 0);
    qk_split<<<qkBlocks, 256>>>(pk, pks, 1.0f, 1);
    vt_split<<<dim3(32, 32), 256>>>(pv, pvh, pvl);

    // Tensor-core attention
    attn_mma<<<dim3(SEQ / 64, BATCH * HEADS), 256, ATTN_SMEM>>>(pqs, pks, pvh, pvl, pa);

    // Output projection
    split_kernel<<<actBlocks, 256>>>((const float4*)pa, pas, 1);
    split_kernel<<<wgtBlocks, 256>>>((const float4*)W_O, pws, 0);
    gemm_mma<<<gg, 512>>>(pas, pws, out);
}

// round 9
// speedup vs baseline: 2.3632x; 1.0730x over previous
#include <cuda_runtime.h>
#include <cuda_bf16.h>
#include <cstdint>

// Problem constants
#define BATCH   2
#define SEQ     2048
#define DMODEL  1024
#define HEADS   16
#define DK      64
#define ROWS    (BATCH * SEQ)          // 4096
#define K2      3072                   // split-bf16 concatenated K (3 * 1024)

// ---------------------------------------------------------------------------
// Scratch (device globals: allocation-free, graph-capture safe)
// ---------------------------------------------------------------------------
__device__ float g_q[ROWS * DMODEL];
__device__ float g_k[ROWS * DMODEL];
__device__ float g_v[ROWS * DMODEL];
__device__ float g_attn[ROWS * DMODEL];
__device__ __nv_bfloat16 g_asplit[(size_t)ROWS * K2];     // activations, split
__device__ __nv_bfloat16 g_wsplit[(size_t)DMODEL * K2];   // weights, split
// attention operands (pre-split, per-head layouts)
__device__ __nv_bfloat16 g_qs[(size_t)32 * SEQ * 192];    // [bh][s][192]  [hi|lo|hi]
__device__ __nv_bfloat16 g_ks[(size_t)32 * SEQ * 192];    // [bh][s][192]  [hi|hi|lo]
__device__ __nv_bfloat16 g_vth[(size_t)32 * DK * SEQ];    // [bh][d][s]    V^T hi
__device__ __nv_bfloat16 g_vtl[(size_t)32 * DK * SEQ];    // [bh][d][s]    V^T lo

// ---------------------------------------------------------------------------
// PTX helpers (sm_80+ features only: cp.async, ldmatrix, mma.sync)
// ---------------------------------------------------------------------------
__device__ __forceinline__ uint32_t smem_u32(const void* p) {
    uint32_t a;
    asm("{ .reg .u64 t; cvta.to.shared.u64 t, %1; cvt.u32.u64 %0, t; }"
        : "=r"(a) : "l"(p));
    return a;
}
__device__ __forceinline__ void cp16(uint32_t saddr, const void* g) {
    asm volatile("cp.async.cg.shared.global [%0], [%1], 16;"
                 :: "r"(saddr), "l"(g) : "memory");
}
__device__ __forceinline__ void cp_commit() {
    asm volatile("cp.async.commit_group;" ::: "memory");
}
__device__ __forceinline__ void cp_wait0() { asm volatile("cp.async.wait_group 0;" ::: "memory"); }
__device__ __forceinline__ void cp_wait2() { asm volatile("cp.async.wait_group 2;" ::: "memory"); }

__device__ __forceinline__ void ldmx4(uint32_t* r, uint32_t addr) {
    asm volatile("ldmatrix.sync.aligned.m8n8.x4.shared.b16 {%0,%1,%2,%3}, [%4];"
                 : "=r"(r[0]), "=r"(r[1]), "=r"(r[2]), "=r"(r[3]) : "r"(addr));
}
__device__ __forceinline__ void mma16816(float* d, const uint32_t* a, const uint32_t* b) {
    asm volatile(
        "mma.sync.aligned.m16n8k16.row.col.f32.bf16.bf16.f32 "
        "{%0,%1,%2,%3}, {%4,%5,%6,%7}, {%8,%9}, {%0,%1,%2,%3};"
        : "+f"(d[0]), "+f"(d[1]), "+f"(d[2]), "+f"(d[3])
        : "r"(a[0]), "r"(a[1]), "r"(a[2]), "r"(a[3]), "r"(b[0]), "r"(b[1]));
}

// ---------------------------------------------------------------------------
// Split-bf16 conversion for projection GEMMs: fp32 [rows,1024] -> bf16 [rows,3072]
// act pattern: [hi | lo | hi];  wgt pattern: [hi | hi | lo]
// ---------------------------------------------------------------------------
__global__ void split_kernel(const float4* __restrict__ x,
                             __nv_bfloat16* __restrict__ y, int act)
{
    size_t i = (size_t)blockIdx.x * blockDim.x + threadIdx.x;
    size_t r  = i >> 8;
    size_t c  = (i & 255) * 4;
    float4 v = x[i];
    float f[4] = {v.x, v.y, v.z, v.w};
    __nv_bfloat16 h[4], l[4];
#pragma unroll
    for (int j = 0; j < 4; j++) {
        h[j] = __float2bfloat16(f[j]);
        l[j] = __float2bfloat16(f[j] - __bfloat162float(h[j]));
    }
    uint2 hv = *(uint2*)h;
    uint2 lv = *(uint2*)l;
    __nv_bfloat16* row = y + r * K2;
    *(uint2*)&row[c] = hv;
    if (act) {
        *(uint2*)&row[1024 + c] = lv;
        *(uint2*)&row[2048 + c] = hv;
    } else {
        *(uint2*)&row[1024 + c] = hv;
        *(uint2*)&row[2048 + c] = lv;
    }
}

// ---------------------------------------------------------------------------
// Q/K split for attention: g_q/g_k fp32 [4096,1024] -> [bh][s][192]
// pat 0 (Q): [hi|lo|hi] (scale folded in);  pat 1 (K): [hi|hi|lo]
// ---------------------------------------------------------------------------
__global__ void qk_split(const float* __restrict__ x, __nv_bfloat16* __restrict__ y,
                         float scale, int pat)
{
    int idx = blockIdx.x * blockDim.x + threadIdx.x;   // pair index (2M)
    int row = idx >> 9;                                // global row (b*2048+s)
    int d2  = (idx & 511) * 2;
    int h   = d2 >> 6;
    int d   = d2 & 63;
    float f0 = x[(size_t)row * 1024 + d2]     * scale;
    float f1 = x[(size_t)row * 1024 + d2 + 1] * scale;
    __nv_bfloat16 h0 = __float2bfloat16(f0), h1 = __float2bfloat16(f1);
    float l0f = f0 - __bfloat162float(h0), l1f = f1 - __bfloat162float(h1);
    __nv_bfloat162 hp = __nv_bfloat162(h0, h1);
    __nv_bfloat162 lp = __nv_bfloat162(__float2bfloat16(l0f), __float2bfloat16(l1f));
    int b = row >> 11, s = row & 2047;
    __nv_bfloat16* dst = y + (((size_t)(b * 16 + h) * SEQ) + s) * 192;
    *(__nv_bfloat162*)(dst + d) = hp;
    if (pat == 0) {
        *(__nv_bfloat162*)(dst + 64 + d)  = lp;
        *(__nv_bfloat162*)(dst + 128 + d) = hp;
    } else {
        *(__nv_bfloat162*)(dst + 64 + d)  = hp;
        *(__nv_bfloat162*)(dst + 128 + d) = lp;
    }
}

// ---------------------------------------------------------------------------
// V transpose+split: g_v fp32 [4096,1024] -> vth/vtl [bh][64][2048]
// ---------------------------------------------------------------------------
__global__ void vt_split(const float* __restrict__ v,
                         __nv_bfloat16* __restrict__ vh, __nv_bfloat16* __restrict__ vl)
{
    __shared__ float t[64][65];
    const int bh = blockIdx.x;        // 32
    const int st = blockIdx.y;        // 32 s-tiles
    const int b = bh >> 4, h = bh & 15;
    const int tid = threadIdx.x;      // 256
    for (int i = tid; i < 64 * 16; i += 256) {
        int r = i >> 4, c4 = (i & 15) * 4;
        float4 val = *(const float4*)&v[((size_t)(b * SEQ + st * 64 + r)) * 1024 + h * 64 + c4];
        t[r][c4] = val.x; t[r][c4 + 1] = val.y; t[r][c4 + 2] = val.z; t[r][c4 + 3] = val.w;
    }
    __syncthreads();
    for (int i = tid; i < 64 * 32; i += 256) {
        int d = i >> 5, sp = (i & 31) * 2;
        float f0 = t[sp][d], f1 = t[sp + 1][d];
        __nv_bfloat16 h0 = __float2bfloat16(f0), h1 = __float2bfloat16(f1);
        __nv_bfloat162 hp = __nv_bfloat162(h0, h1);
        __nv_bfloat162 lp = __nv_bfloat162(
            __float2bfloat16(f0 - __bfloat162float(h0)),
            __float2bfloat16(f1 - __bfloat162float(h1)));
        size_t off = ((size_t)bh * 64 + d) * SEQ + st * 64 + sp;
        *(__nv_bfloat162*)(vh + off) = hp;
        *(__nv_bfloat162*)(vl + off) = lp;
    }
}

// ---------------------------------------------------------------------------
// mma.sync bf16 NT GEMM (projections): 4-stage cp.async pipeline.
// Tile 128(M) x 256(N), BK=32, 512 threads (16 warps, 64x32 warp tiles).
// One __syncthreads per chunk; loads for chunk i+3 issued BEFORE mma of i.
// Dynamic smem: 4 x (8KB A + 16KB B) = 96KB.
// ---------------------------------------------------------------------------
#define GM 128
#define GN 256
#define BKE 32
#define CHUNKB 64
#define NCHUNK (K2 / BKE)       // 96
#define GSTG_A 8192
#define GSTG_B 16384
#define GB_OFF (4 * GSTG_A)     // B region starts at 32KB
#define GEMM_SMEM (4 * (GSTG_A + GSTG_B))   // 98304

__global__ __launch_bounds__(512, 1)
void gemm_mma(const __nv_bfloat16* __restrict__ A, const __nv_bfloat16* __restrict__ B,
              float* __restrict__ C)
{
    extern __shared__ __align__(128) uint8_t dynsm[];
    const uint32_t smbase = smem_u32(dynsm);

    const int tid    = threadIdx.x;
    const int wid    = tid >> 5;
    const int lane   = tid & 31;
    const int warp_m = wid >> 3;
    const int warp_n = wid & 7;
    const int rowBase = blockIdx.y * GM;
    const int colBase = blockIdx.x * GN;

    float acc[4][4][4];
#pragma unroll
    for (int i = 0; i < 4; i++)
#pragma unroll
        for (int j = 0; j < 4; j++)
#pragma unroll
            for (int t = 0; t < 4; t++) acc[i][j][t] = 0.f;

    const int a_moff = ((lane >> 3) & 1) * 8 + (lane & 7);
    const int a_half = lane >> 4;
    const int b_noff = (lane >> 4) * 8 + (lane & 7);
    const int b_half = (lane >> 3) & 1;

    auto load_chunk = [&](int chunk, int stg) {
        const int k0 = chunk * BKE;
        const uint32_t abase = smbase + stg * GSTG_A;
        const uint32_t bbase = smbase + GB_OFF + stg * GSTG_B;
#pragma unroll
        for (int it = 0; it < 3; it++) {
            int u = tid + it * 512;
            if (u < 512) {
                int r = u >> 2, c = u & 3;
                cp16(abase + r * CHUNKB + ((c ^ (r & 3)) * 16),
                     A + (size_t)(rowBase + r) * K2 + k0 + c * 8);
            } else {
                int v2 = u - 512;
                int r = v2 >> 2, c = v2 & 3;
                cp16(bbase + r * CHUNKB + ((c ^ (r & 3)) * 16),
                     B + (size_t)(colBase + r) * K2 + k0 + c * 8);
            }
        }
        cp_commit();
    };

    // Prologue: 3 stages in flight
    load_chunk(0, 0);
    load_chunk(1, 1);
    load_chunk(2, 2);

    for (int i = 0; i < NCHUNK; i++) {
        const int stg = i & 3;
        cp_wait2();                 // chunk i resident (<=2 newer groups pending)
        __syncthreads();            // also protects reuse of stage (i+3)&3 == (i-1)&3

        // Issue loads for chunk i+3 BEFORE compute (empty commit keeps accounting)
        if (i + 3 < NCHUNK) load_chunk(i + 3, (i + 3) & 3);
        else                cp_commit();

        const uint32_t abase = smbase + stg * GSTG_A;
        const uint32_t bbase = smbase + GB_OFF + stg * GSTG_B;
#pragma unroll
        for (int ks = 0; ks < 2; ks++) {
            uint32_t afrag[4][4], bfrag[4][2];
#pragma unroll
            for (int fi = 0; fi < 4; fi++) {
                int m = warp_m * 64 + fi * 16 + a_moff;
                uint32_t addr = abase + m * CHUNKB
                              + (((ks * 2 + a_half) ^ (a_moff & 3)) * 16);
                ldmx4(afrag[fi], addr);
            }
#pragma unroll
            for (int jj = 0; jj < 2; jj++) {
                int n = warp_n * 32 + jj * 16 + b_noff;
                uint32_t addr = bbase + n * CHUNKB
                              + (((ks * 2 + b_half) ^ (b_noff & 3)) * 16);
                uint32_t r[4];
                ldmx4(r, addr);
                bfrag[jj * 2][0]     = r[0];
                bfrag[jj * 2][1]     = r[1];
                bfrag[jj * 2 + 1][0] = r[2];
                bfrag[jj * 2 + 1][1] = r[3];
            }
#pragma unroll
            for (int fi = 0; fi < 4; fi++)
#pragma unroll
                for (int fj = 0; fj < 4; fj++)
                    mma16816(acc[fi][fj], afrag[fi], bfrag[fj]);
        }
    }

    const int erow = (lane >> 2);
    const int ecol = (lane & 3) * 2;
#pragma unroll
    for (int fi = 0; fi < 4; fi++) {
#pragma unroll
        for (int fj = 0; fj < 4; fj++) {
            int row = rowBase + warp_m * 64 + fi * 16 + erow;
            int col = colBase + warp_n * 32 + fj * 8 + ecol;
            *(float2*)&C[(size_t)row * DMODEL + col] =
                make_float2(acc[fi][fj][0], acc[fi][fj][1]);
            *(float2*)&C[(size_t)(row + 8) * DMODEL + col] =
                make_float2(acc[fi][fj][2], acc[fi][fj][3]);
        }
    }
}

// ---------------------------------------------------------------------------
// Tensor-core causal flash attention (validated R7, unchanged).
// ---------------------------------------------------------------------------
#define APITCHB 400                   // bytes per smem row
#define TILEB   (64 * APITCHB)        // 25600
#define SQ_OFF  0
#define SK_OFF  TILEB
#define SV_OFF  (2 * TILEB)
#define SP_OFF  (3 * TILEB)
#define SST_OFF (4 * TILEB)           // state floats
#define ATTN_SMEM (SST_OFF + 512 * 4) // 104448

__global__ __launch_bounds__(256, 2)
void attn_mma(const __nv_bfloat16* __restrict__ qs, const __nv_bfloat16* __restrict__ ks,
              const __nv_bfloat16* __restrict__ vth, const __nv_bfloat16* __restrict__ vtl,
              float* __restrict__ out)
{
    extern __shared__ char sm[];
    const uint32_t sb = smem_u32(sm);
    float* st   = (float*)(sm + SST_OFF);
    float* mrow = st;            // [64]
    float* lrow = st + 64;       // [64]
    float* arow = st + 128;      // [64]
    float* mnew = st + 192;      // [64]
    float* pmax = st + 256;      // [2][64]
    float* psum = st + 384;      // [2][64]

    const int tid  = threadIdx.x;
    const int wid  = tid >> 5;
    const int lane = tid & 31;
    const int wm   = wid & 3;          // 16-row strip
    const int wn   = wid >> 2;         // 32-col strip
    const int qb   = blockIdx.x;
    const int bh   = blockIdx.y;

    const __nv_bfloat16* qsrc = qs  + ((size_t)bh * SEQ + qb * 64) * 192;
    const __nv_bfloat16* ksrc = ks  + (size_t)bh * SEQ * 192;
    const __nv_bfloat16* vhs  = vth + (size_t)bh * 64 * SEQ;
    const __nv_bfloat16* vls  = vtl + (size_t)bh * 64 * SEQ;

    // Q' load (once)
    for (int u = tid; u < 1536; u += 256) {
        int r = u / 24, c = u % 24;
        cp16(sb + SQ_OFF + r * APITCHB + c * 16, qsrc + (size_t)r * 192 + c * 8);
    }
    cp_commit();

    if (tid < 64) { mrow[tid] = -1e30f; lrow[tid] = 0.f; }

    float acco[4][4];
#pragma unroll
    for (int j = 0; j < 4; j++)
#pragma unroll
        for (int t = 0; t < 4; t++) acco[j][t] = 0.f;

    const int a_moff = ((lane >> 3) & 1) * 8 + (lane & 7);
    const int a_half = lane >> 4;
    const int b_noff = (lane >> 4) * 8 + (lane & 7);
    const int b_half = (lane >> 3) & 1;
    const int erow   = lane >> 2;
    const int ecol   = (lane & 3) * 2;
    const int r0 = wm * 16 + erow, r1 = r0 + 8;

    for (int kb = 0; kb <= qb; kb++) {
        // K' tile
        for (int u = tid; u < 1536; u += 256) {
            int r = u / 24, c = u % 24;
            cp16(sb + SK_OFF + r * APITCHB + c * 16,
                 ksrc + ((size_t)(kb * 64 + r)) * 192 + c * 8);
        }
        // VT' tile: cols [0:16) chunks from hi (dup), [16:24) from lo
        for (int u = tid; u < 1536; u += 256) {
            int r = u / 24, c = u % 24;
            const __nv_bfloat16* src = (c < 16)
                ? (vhs + (size_t)r * SEQ + kb * 64 + (c & 7) * 8)
                : (vls + (size_t)r * SEQ + kb * 64 + (c - 16) * 8);
            cp16(sb + SV_OFF + r * APITCHB + c * 16, src);
        }
        cp_commit();
        cp_wait0();
        __syncthreads();

        // ---- S = Q' K'^T  (12 k-steps) ----
        float accs[4][4];
#pragma unroll
        for (int j = 0; j < 4; j++)
#pragma unroll
            for (int t = 0; t < 4; t++) accs[j][t] = 0.f;

#pragma unroll
        for (int ks_ = 0; ks_ < 12; ks_++) {
            uint32_t af[4], bf[4][2];
            ldmx4(af, sb + SQ_OFF + (wm * 16 + a_moff) * APITCHB + ks_ * 32 + a_half * 16);
#pragma unroll
            for (int jj = 0; jj < 2; jj++) {
                uint32_t r[4];
                ldmx4(r, sb + SK_OFF + (wn * 32 + jj * 16 + b_noff) * APITCHB
                         + ks_ * 32 + b_half * 16);
                bf[jj * 2][0] = r[0]; bf[jj * 2][1] = r[1];
                bf[jj * 2 + 1][0] = r[2]; bf[jj * 2 + 1][1] = r[3];
            }
#pragma unroll
            for (int fj = 0; fj < 4; fj++) mma16816(accs[fj], af, bf[fj]);
        }

        // causal mask (diagonal tile)
        if (kb == qb) {
#pragma unroll
            for (int fj = 0; fj < 4; fj++) {
                int gc = wn * 32 + fj * 8 + ecol;
                if (gc     > r0) accs[fj][0] = -1e30f;
                if (gc + 1 > r0) accs[fj][1] = -1e30f;
                if (gc     > r1) accs[fj][2] = -1e30f;
                if (gc + 1 > r1) accs[fj][3] = -1e30f;
            }
        }

        // ---- row maxes ----
        float lm0 = -1e30f, lm1 = -1e30f;
#pragma unroll
        for (int fj = 0; fj < 4; fj++) {
            lm0 = fmaxf(lm0, fmaxf(accs[fj][0], accs[fj][1]));
            lm1 = fmaxf(lm1, fmaxf(accs[fj][2], accs[fj][3]));
        }
        lm0 = fmaxf(lm0, __shfl_xor_sync(0xFFFFFFFF, lm0, 1));
        lm0 = fmaxf(lm0, __shfl_xor_sync(0xFFFFFFFF, lm0, 2));
        lm1 = fmaxf(lm1, __shfl_xor_sync(0xFFFFFFFF, lm1, 1));
        lm1 = fmaxf(lm1, __shfl_xor_sync(0xFFFFFFFF, lm1, 2));
        if ((lane & 3) == 0) {
            pmax[wn * 64 + r0] = lm0;
            pmax[wn * 64 + r1] = lm1;
        }
        __syncthreads();

        if (tid < 64) {
            float mo = mrow[tid];
            float mn = fmaxf(mo, fmaxf(pmax[tid], pmax[64 + tid]));
            mnew[tid] = mn;
            arow[tid] = __expf(mo - mn);
            mrow[tid] = mn;
        }
        __syncthreads();

        // ---- exp, write P' (hi|lo|hi), partial sums, rescale O ----
        const float mn0 = mnew[r0], mn1 = mnew[r1];
        const float al0 = arow[r0], al1 = arow[r1];
        float s0 = 0.f, s1 = 0.f;
#pragma unroll
        for (int fj = 0; fj < 4; fj++) {
            int kc = wn * 32 + fj * 8 + ecol;
            float p00 = __expf(accs[fj][0] - mn0);
            float p01 = __expf(accs[fj][1] - mn0);
            float p10 = __expf(accs[fj][2] - mn1);
            float p11 = __expf(accs[fj][3] - mn1);
            s0 += p00 + p01;
            s1 += p10 + p11;
            __nv_bfloat16 h00 = __float2bfloat16(p00), h01 = __float2bfloat16(p01);
            __nv_bfloat16 h10 = __float2bfloat16(p10), h11 = __float2bfloat16(p11);
            __nv_bfloat162 hp0 = __nv_bfloat162(h00, h01);
            __nv_bfloat162 hp1 = __nv_bfloat162(h10, h11);
            __nv_bfloat162 lp0 = __nv_bfloat162(
                __float2bfloat16(p00 - __bfloat162float(h00)),
                __float2bfloat16(p01 - __bfloat162float(h01)));
            __nv_bfloat162 lp1 = __nv_bfloat162(
                __float2bfloat16(p10 - __bfloat162float(h10)),
                __float2bfloat16(p11 - __bfloat162float(h11)));
            char* pr0 = sm + SP_OFF + r0 * APITCHB;
            char* pr1 = sm + SP_OFF + r1 * APITCHB;
            *(__nv_bfloat162*)(pr0 + kc * 2)       = hp0;
            *(__nv_bfloat162*)(pr0 + 128 + kc * 2) = lp0;
            *(__nv_bfloat162*)(pr0 + 256 + kc * 2) = hp0;
            *(__nv_bfloat162*)(pr1 + kc * 2)       = hp1;
            *(__nv_bfloat162*)(pr1 + 128 + kc * 2) = lp1;
            *(__nv_bfloat162*)(pr1 + 256 + kc * 2) = hp1;
        }
        s0 += __shfl_xor_sync(0xFFFFFFFF, s0, 1);
        s0 += __shfl_xor_sync(0xFFFFFFFF, s0, 2);
        s1 += __shfl_xor_sync(0xFFFFFFFF, s1, 1);
        s1 += __shfl_xor_sync(0xFFFFFFFF, s1, 2);
        if ((lane & 3) == 0) {
            psum[wn * 64 + r0] = s0;
            psum[wn * 64 + r1] = s1;
        }
#pragma unroll
        for (int fj = 0; fj < 4; fj++) {
            acco[fj][0] *= al0; acco[fj][1] *= al0;
            acco[fj][2] *= al1; acco[fj][3] *= al1;
        }
        __syncthreads();
        if (tid < 64)
            lrow[tid] = lrow[tid] * arow[tid] + psum[tid] + psum[64 + tid];

        // ---- O += P' VT'^T  (12 k-steps) ----
#pragma unroll
        for (int ks_ = 0; ks_ < 12; ks_++) {
            uint32_t af[4], bf[4][2];
            ldmx4(af, sb + SP_OFF + (wm * 16 + a_moff) * APITCHB + ks_ * 32 + a_half * 16);
#pragma unroll
            for (int jj = 0; jj < 2; jj++) {
                uint32_t r[4];
                ldmx4(r, sb + SV_OFF + (wn * 32 + jj * 16 + b_noff) * APITCHB
                         + ks_ * 32 + b_half * 16);
                bf[jj * 2][0] = r[0]; bf[jj * 2][1] = r[1];
                bf[jj * 2 + 1][0] = r[2]; bf[jj * 2 + 1][1] = r[3];
            }
#pragma unroll
            for (int fj = 0; fj < 4; fj++) mma16816(acco[fj], af, bf[fj]);
        }
        __syncthreads();
    }

    // ---- finalize: O /= l, write [b, qb*64+q, h*64+d] ----
    const int b = bh >> 4, h = bh & 15;
    const float il0 = 1.f / lrow[r0];
    const float il1 = 1.f / lrow[r1];
    const size_t grow0 = (size_t)(b * SEQ + qb * 64 + r0) * DMODEL;
    const size_t grow1 = (size_t)(b * SEQ + qb * 64 + r1) * DMODEL;
#pragma unroll
    for (int fj = 0; fj < 4; fj++) {
        int col = h * 64 + wn * 32 + fj * 8 + ecol;
        *(float2*)&out[grow0 + col] = make_float2(acco[fj][0] * il0, acco[fj][1] * il0);
        *(float2*)&out[grow1 + col] = make_float2(acco[fj][2] * il1, acco[fj][3] * il1);
    }
}

// ---------------------------------------------------------------------------
// Launch
// ---------------------------------------------------------------------------
extern "C" void kernel_launch(void* const* d_in, const int* in_sizes, int n_in,
                              void* d_out, int out_size)
{
    const float* Q   = (const float*)d_in[0];
    const float* K   = (const float*)d_in[1];
    const float* V   = (const float*)d_in[2];
    const float* W_Q = (const float*)d_in[4];
    const float* W_K = (const float*)d_in[5];
    const float* W_V = (const float*)d_in[6];
    const float* W_O = (const float*)d_in[7];
    float* out = (float*)d_out;

    float *pq, *pk, *pv, *pa;
    __nv_bfloat16 *pas, *pws, *pqs, *pks, *pvh, *pvl;
    cudaGetSymbolAddress((void**)&pq, g_q);
    cudaGetSymbolAddress((void**)&pk, g_k);
    cudaGetSymbolAddress((void**)&pv, g_v);
    cudaGetSymbolAddress((void**)&pa, g_attn);
    cudaGetSymbolAddress((void**)&pas, g_asplit);
    cudaGetSymbolAddress((void**)&pws, g_wsplit);
    cudaGetSymbolAddress((void**)&pqs, g_qs);
    cudaGetSymbolAddress((void**)&pks, g_ks);
    cudaGetSymbolAddress((void**)&pvh, g_vth);
    cudaGetSymbolAddress((void**)&pvl, g_vtl);

    cudaFuncSetAttribute(gemm_mma,
                         cudaFuncAttributeMaxDynamicSharedMemorySize, GEMM_SMEM);
    cudaFuncSetAttribute(attn_mma,
                         cudaFuncAttributeMaxDynamicSharedMemorySize, ATTN_SMEM);

    const int actBlocks = ROWS * DMODEL / 4 / 256;     // 4096
    const int wgtBlocks = DMODEL * DMODEL / 4 / 256;   // 1024
    const int qkBlocks  = ROWS * DMODEL / 2 / 256;     // 8192
    dim3 gg(DMODEL / GN, ROWS / GM);                   // (4, 32)

    // Projections
    split_kernel<<<actBlocks, 256>>>((const float4*)Q, pas, 1);
    split_kernel<<<wgtBlocks, 256>>>((const float4*)W_Q, pws, 0);
    gemm_mma<<<gg, 512, GEMM_SMEM>>>(pas, pws, pq);
    split_kernel<<<actBlocks, 256>>>((const float4*)K, pas, 1);
    split_kernel<<<wgtBlocks, 256>>>((const float4*)W_K, pws, 0);
    gemm_mma<<<gg, 512, GEMM_SMEM>>>(pas, pws, pk);
    split_kernel<<<actBlocks, 256>>>((const float4*)V, pas, 1);
    split_kernel<<<wgtBlocks, 256>>>((const float4*)W_V, pws, 0);
    gemm_mma<<<gg, 512, GEMM_SMEM>>>(pas, pws, pv);

    // Attention operand prep
    qk_split<<<qkBlocks, 256>>>(pq, pqs, 0.125f, 0);
    qk_split<<<qkBlocks, 256>>>(pk, pks, 1.0f, 1);
    vt_split<<<dim3(32, 32), 256>>>(pv, pvh, pvl);

    // Tensor-core attention
    attn_mma<<<dim3(SEQ / 64, BATCH * HEADS), 256, ATTN_SMEM>>>(pqs, pks, pvh, pvl, pa);

    // Output projection
    split_kernel<<<actBlocks, 256>>>((const float4*)pa, pas, 1);
    split_kernel<<<wgtBlocks, 256>>>((const float4*)W_O, pws, 0);
    gemm_mma<<<gg, 512, GEMM_SMEM>>>(pas, pws, out);
}

// round 10
// speedup vs baseline: 2.6753x; 1.1321x over previous
#include <cuda_runtime.h>
#include <cuda_bf16.h>
#include <cstdint>

// Problem constants
#define BATCH   2
#define SEQ     2048
#define DMODEL  1024
#define HEADS   16
#define DK      64
#define ROWS    (BATCH * SEQ)          // 4096
#define K2      3072                   // split-bf16 concatenated K (3 * 1024)

// ---------------------------------------------------------------------------
// Scratch (device globals: allocation-free, graph-capture safe)
// ---------------------------------------------------------------------------
__device__ float g_q[ROWS * DMODEL];
__device__ float g_k[ROWS * DMODEL];
__device__ float g_v[ROWS * DMODEL];
__device__ float g_attn[ROWS * DMODEL];
__device__ __nv_bfloat16 g_asplit[(size_t)ROWS * K2];     // activations, split
__device__ __nv_bfloat16 g_wsplit[(size_t)DMODEL * K2];   // weights, split
// attention operands (pre-split, per-head layouts)
__device__ __nv_bfloat16 g_qs[(size_t)32 * SEQ * 192];    // [bh][s][192]  [hi|lo|hi]
__device__ __nv_bfloat16 g_ks[(size_t)32 * SEQ * 192];    // [bh][s][192]  [hi|hi|lo]
__device__ __nv_bfloat16 g_vth[(size_t)32 * DK * SEQ];    // [bh][d][s]    V^T hi
__device__ __nv_bfloat16 g_vtl[(size_t)32 * DK * SEQ];    // [bh][d][s]    V^T lo

// ---------------------------------------------------------------------------
// PTX helpers (sm_80+ features only: cp.async, ldmatrix, mma.sync)
// ---------------------------------------------------------------------------
__device__ __forceinline__ uint32_t smem_u32(const void* p) {
    uint32_t a;
    asm("{ .reg .u64 t; cvta.to.shared.u64 t, %1; cvt.u32.u64 %0, t; }"
        : "=r"(a) : "l"(p));
    return a;
}
__device__ __forceinline__ void cp16(uint32_t saddr, const void* g) {
    asm volatile("cp.async.cg.shared.global [%0], [%1], 16;"
                 :: "r"(saddr), "l"(g) : "memory");
}
__device__ __forceinline__ void cp_commit() {
    asm volatile("cp.async.commit_group;" ::: "memory");
}
__device__ __forceinline__ void cp_wait0() { asm volatile("cp.async.wait_group 0;" ::: "memory"); }
__device__ __forceinline__ void cp_wait2() { asm volatile("cp.async.wait_group 2;" ::: "memory"); }

__device__ __forceinline__ void ldmx4(uint32_t* r, uint32_t addr) {
    asm volatile("ldmatrix.sync.aligned.m8n8.x4.shared.b16 {%0,%1,%2,%3}, [%4];"
                 : "=r"(r[0]), "=r"(r[1]), "=r"(r[2]), "=r"(r[3]) : "r"(addr));
}
__device__ __forceinline__ void mma16816(float* d, const uint32_t* a, const uint32_t* b) {
    asm volatile(
        "mma.sync.aligned.m16n8k16.row.col.f32.bf16.bf16.f32 "
        "{%0,%1,%2,%3}, {%4,%5,%6,%7}, {%8,%9}, {%0,%1,%2,%3};"
        : "+f"(d[0]), "+f"(d[1]), "+f"(d[2]), "+f"(d[3])
        : "r"(a[0]), "r"(a[1]), "r"(a[2]), "r"(a[3]), "r"(b[0]), "r"(b[1]));
}

// ---------------------------------------------------------------------------
// Split-bf16 conversion for projection GEMMs: fp32 [rows,1024] -> bf16 [rows,3072]
// act pattern: [hi | lo | hi];  wgt pattern: [hi | hi | lo]
// ---------------------------------------------------------------------------
__global__ void split_kernel(const float4* __restrict__ x,
                             __nv_bfloat16* __restrict__ y, int act)
{
    size_t i = (size_t)blockIdx.x * blockDim.x + threadIdx.x;
    size_t r  = i >> 8;
    size_t c  = (i & 255) * 4;
    float4 v = x[i];
    float f[4] = {v.x, v.y, v.z, v.w};
    __nv_bfloat16 h[4], l[4];
#pragma unroll
    for (int j = 0; j < 4; j++) {
        h[j] = __float2bfloat16(f[j]);
        l[j] = __float2bfloat16(f[j] - __bfloat162float(h[j]));
    }
    uint2 hv = *(uint2*)h;
    uint2 lv = *(uint2*)l;
    __nv_bfloat16* row = y + r * K2;
    *(uint2*)&row[c] = hv;
    if (act) {
        *(uint2*)&row[1024 + c] = lv;
        *(uint2*)&row[2048 + c] = hv;
    } else {
        *(uint2*)&row[1024 + c] = hv;
        *(uint2*)&row[2048 + c] = lv;
    }
}

// ---------------------------------------------------------------------------
// Q/K split for attention: g_q/g_k fp32 [4096,1024] -> [bh][s][192]
// pat 0 (Q): [hi|lo|hi] (scale folded in);  pat 1 (K): [hi|hi|lo]
// ---------------------------------------------------------------------------
__global__ void qk_split(const float* __restrict__ x, __nv_bfloat16* __restrict__ y,
                         float scale, int pat)
{
    int idx = blockIdx.x * blockDim.x + threadIdx.x;   // pair index (2M)
    int row = idx >> 9;                                // global row (b*2048+s)
    int d2  = (idx & 511) * 2;
    int h   = d2 >> 6;
    int d   = d2 & 63;
    float f0 = x[(size_t)row * 1024 + d2]     * scale;
    float f1 = x[(size_t)row * 1024 + d2 + 1] * scale;
    __nv_bfloat16 h0 = __float2bfloat16(f0), h1 = __float2bfloat16(f1);
    float l0f = f0 - __bfloat162float(h0), l1f = f1 - __bfloat162float(h1);
    __nv_bfloat162 hp = __nv_bfloat162(h0, h1);
    __nv_bfloat162 lp = __nv_bfloat162(__float2bfloat16(l0f), __float2bfloat16(l1f));
    int b = row >> 11, s = row & 2047;
    __nv_bfloat16* dst = y + (((size_t)(b * 16 + h) * SEQ) + s) * 192;
    *(__nv_bfloat162*)(dst + d) = hp;
    if (pat == 0) {
        *(__nv_bfloat162*)(dst + 64 + d)  = lp;
        *(__nv_bfloat162*)(dst + 128 + d) = hp;
    } else {
        *(__nv_bfloat162*)(dst + 64 + d)  = hp;
        *(__nv_bfloat162*)(dst + 128 + d) = lp;
    }
}

// ---------------------------------------------------------------------------
// V transpose+split: g_v fp32 [4096,1024] -> vth/vtl [bh][64][2048]
// ---------------------------------------------------------------------------
__global__ void vt_split(const float* __restrict__ v,
                         __nv_bfloat16* __restrict__ vh, __nv_bfloat16* __restrict__ vl)
{
    __shared__ float t[64][65];
    const int bh = blockIdx.x;        // 32
    const int st = blockIdx.y;        // 32 s-tiles
    const int b = bh >> 4, h = bh & 15;
    const int tid = threadIdx.x;      // 256
    for (int i = tid; i < 64 * 16; i += 256) {
        int r = i >> 4, c4 = (i & 15) * 4;
        float4 val = *(const float4*)&v[((size_t)(b * SEQ + st * 64 + r)) * 1024 + h * 64 + c4];
        t[r][c4] = val.x; t[r][c4 + 1] = val.y; t[r][c4 + 2] = val.z; t[r][c4 + 3] = val.w;
    }
    __syncthreads();
    for (int i = tid; i < 64 * 32; i += 256) {
        int d = i >> 5, sp = (i & 31) * 2;
        float f0 = t[sp][d], f1 = t[sp + 1][d];
        __nv_bfloat16 h0 = __float2bfloat16(f0), h1 = __float2bfloat16(f1);
        __nv_bfloat162 hp = __nv_bfloat162(h0, h1);
        __nv_bfloat162 lp = __nv_bfloat162(
            __float2bfloat16(f0 - __bfloat162float(h0)),
            __float2bfloat16(f1 - __bfloat162float(h1)));
        size_t off = ((size_t)bh * 64 + d) * SEQ + st * 64 + sp;
        *(__nv_bfloat162*)(vh + off) = hp;
        *(__nv_bfloat162*)(vl + off) = lp;
    }
}

// ---------------------------------------------------------------------------
// mma.sync bf16 NT GEMM (projections): 4-stage cp.async pipeline.
// Tile 128(M) x 256(N), BK=32, 512 threads (16 warps, 64x32 warp tiles).
// Swizzle key (r>>1)&3: rows sharing a 128B bank base (r, r+2, r+4, r+6)
// get 4 distinct 16B chunks -> conflict-free ldmatrix phases.
// Dynamic smem: 4 x (8KB A + 16KB B) = 96KB.
// ---------------------------------------------------------------------------
#define GM 128
#define GN 256
#define BKE 32
#define CHUNKB 64
#define NCHUNK (K2 / BKE)       // 96
#define GSTG_A 8192
#define GSTG_B 16384
#define GB_OFF (4 * GSTG_A)     // B region starts at 32KB
#define GEMM_SMEM (4 * (GSTG_A + GSTG_B))   // 98304

__global__ __launch_bounds__(512, 1)
void gemm_mma(const __nv_bfloat16* __restrict__ A, const __nv_bfloat16* __restrict__ B,
              float* __restrict__ C)
{
    extern __shared__ __align__(128) uint8_t dynsm[];
    const uint32_t smbase = smem_u32(dynsm);

    const int tid    = threadIdx.x;
    const int wid    = tid >> 5;
    const int lane   = tid & 31;
    const int warp_m = wid >> 3;
    const int warp_n = wid & 7;
    const int rowBase = blockIdx.y * GM;
    const int colBase = blockIdx.x * GN;

    float acc[4][4][4];
#pragma unroll
    for (int i = 0; i < 4; i++)
#pragma unroll
        for (int j = 0; j < 4; j++)
#pragma unroll
            for (int t = 0; t < 4; t++) acc[i][j][t] = 0.f;

    const int a_moff = ((lane >> 3) & 1) * 8 + (lane & 7);
    const int a_half = lane >> 4;
    const int b_noff = (lane >> 4) * 8 + (lane & 7);
    const int b_half = (lane >> 3) & 1;
    const int a_key  = (a_moff >> 1) & 3;   // == (m>>1)&3 (row bases are mult of 16)
    const int b_key  = (b_noff >> 1) & 3;

    auto load_chunk = [&](int chunk, int stg) {
        const int k0 = chunk * BKE;
        const uint32_t abase = smbase + stg * GSTG_A;
        const uint32_t bbase = smbase + GB_OFF + stg * GSTG_B;
#pragma unroll
        for (int it = 0; it < 3; it++) {
            int u = tid + it * 512;
            if (u < 512) {
                int r = u >> 2, c = u & 3;
                cp16(abase + r * CHUNKB + ((c ^ ((r >> 1) & 3)) * 16),
                     A + (size_t)(rowBase + r) * K2 + k0 + c * 8);
            } else {
                int v2 = u - 512;
                int r = v2 >> 2, c = v2 & 3;
                cp16(bbase + r * CHUNKB + ((c ^ ((r >> 1) & 3)) * 16),
                     B + (size_t)(colBase + r) * K2 + k0 + c * 8);
            }
        }
        cp_commit();
    };

    // Prologue: 3 stages in flight
    load_chunk(0, 0);
    load_chunk(1, 1);
    load_chunk(2, 2);

    for (int i = 0; i < NCHUNK; i++) {
        const int stg = i & 3;
        cp_wait2();                 // chunk i resident (<=2 newer groups pending)
        __syncthreads();            // also protects reuse of stage (i+3)&3 == (i-1)&3

        // Issue loads for chunk i+3 BEFORE compute (empty commit keeps accounting)
        if (i + 3 < NCHUNK) load_chunk(i + 3, (i + 3) & 3);
        else                cp_commit();

        const uint32_t abase = smbase + stg * GSTG_A;
        const uint32_t bbase = smbase + GB_OFF + stg * GSTG_B;
#pragma unroll
        for (int ks = 0; ks < 2; ks++) {
            uint32_t afrag[4][4], bfrag[4][2];
#pragma unroll
            for (int fi = 0; fi < 4; fi++) {
                int m = warp_m * 64 + fi * 16 + a_moff;
                uint32_t addr = abase + m * CHUNKB
                              + (((ks * 2 + a_half) ^ a_key) * 16);
                ldmx4(afrag[fi], addr);
            }
#pragma unroll
            for (int jj = 0; jj < 2; jj++) {
                int n = warp_n * 32 + jj * 16 + b_noff;
                uint32_t addr = bbase + n * CHUNKB
                              + (((ks * 2 + b_half) ^ b_key) * 16);
                uint32_t r[4];
                ldmx4(r, addr);
                bfrag[jj * 2][0]     = r[0];
                bfrag[jj * 2][1]     = r[1];
                bfrag[jj * 2 + 1][0] = r[2];
                bfrag[jj * 2 + 1][1] = r[3];
            }
#pragma unroll
            for (int fi = 0; fi < 4; fi++)
#pragma unroll
                for (int fj = 0; fj < 4; fj++)
                    mma16816(acc[fi][fj], afrag[fi], bfrag[fj]);
        }
    }

    const int erow = (lane >> 2);
    const int ecol = (lane & 3) * 2;
#pragma unroll
    for (int fi = 0; fi < 4; fi++) {
#pragma unroll
        for (int fj = 0; fj < 4; fj++) {
            int row = rowBase + warp_m * 64 + fi * 16 + erow;
            int col = colBase + warp_n * 32 + fj * 8 + ecol;
            *(float2*)&C[(size_t)row * DMODEL + col] =
                make_float2(acc[fi][fj][0], acc[fi][fj][1]);
            *(float2*)&C[(size_t)(row + 8) * DMODEL + col] =
                make_float2(acc[fi][fj][2], acc[fi][fj][3]);
        }
    }
}

// ---------------------------------------------------------------------------
// Tensor-core causal flash attention (validated R7, unchanged).
// 400B pitch rotates bank base 16B/row -> ldmatrix already conflict-free.
// ---------------------------------------------------------------------------
#define APITCHB 400                   // bytes per smem row
#define TILEB   (64 * APITCHB)        // 25600
#define SQ_OFF  0
#define SK_OFF  TILEB
#define SV_OFF  (2 * TILEB)
#define SP_OFF  (3 * TILEB)
#define SST_OFF (4 * TILEB)           // state floats
#define ATTN_SMEM (SST_OFF + 512 * 4) // 104448

__global__ __launch_bounds__(256, 2)
void attn_mma(const __nv_bfloat16* __restrict__ qs, const __nv_bfloat16* __restrict__ ks,
              const __nv_bfloat16* __restrict__ vth, const __nv_bfloat16* __restrict__ vtl,
              float* __restrict__ out)
{
    extern __shared__ char sm[];
    const uint32_t sb = smem_u32(sm);
    float* st   = (float*)(sm + SST_OFF);
    float* mrow = st;            // [64]
    float* lrow = st + 64;       // [64]
    float* arow = st + 128;      // [64]
    float* mnew = st + 192;      // [64]
    float* pmax = st + 256;      // [2][64]
    float* psum = st + 384;      // [2][64]

    const int tid  = threadIdx.x;
    const int wid  = tid >> 5;
    const int lane = tid & 31;
    const int wm   = wid & 3;          // 16-row strip
    const int wn   = wid >> 2;         // 32-col strip
    const int qb   = blockIdx.x;
    const int bh   = blockIdx.y;

    const __nv_bfloat16* qsrc = qs  + ((size_t)bh * SEQ + qb * 64) * 192;
    const __nv_bfloat16* ksrc = ks  + (size_t)bh * SEQ * 192;
    const __nv_bfloat16* vhs  = vth + (size_t)bh * 64 * SEQ;
    const __nv_bfloat16* vls  = vtl + (size_t)bh * 64 * SEQ;

    // Q' load (once)
    for (int u = tid; u < 1536; u += 256) {
        int r = u / 24, c = u % 24;
        cp16(sb + SQ_OFF + r * APITCHB + c * 16, qsrc + (size_t)r * 192 + c * 8);
    }
    cp_commit();

    if (tid < 64) { mrow[tid] = -1e30f; lrow[tid] = 0.f; }

    float acco[4][4];
#pragma unroll
    for (int j = 0; j < 4; j++)
#pragma unroll
        for (int t = 0; t < 4; t++) acco[j][t] = 0.f;

    const int a_moff = ((lane >> 3) & 1) * 8 + (lane & 7);
    const int a_half = lane >> 4;
    const int b_noff = (lane >> 4) * 8 + (lane & 7);
    const int b_half = (lane >> 3) & 1;
    const int erow   = lane >> 2;
    const int ecol   = (lane & 3) * 2;
    const int r0 = wm * 16 + erow, r1 = r0 + 8;

    for (int kb = 0; kb <= qb; kb++) {
        // K' tile
        for (int u = tid; u < 1536; u += 256) {
            int r = u / 24, c = u % 24;
            cp16(sb + SK_OFF + r * APITCHB + c * 16,
                 ksrc + ((size_t)(kb * 64 + r)) * 192 + c * 8);
        }
        // VT' tile: cols [0:16) chunks from hi (dup), [16:24) from lo
        for (int u = tid; u < 1536; u += 256) {
            int r = u / 24, c = u % 24;
            const __nv_bfloat16* src = (c < 16)
                ? (vhs + (size_t)r * SEQ + kb * 64 + (c & 7) * 8)
                : (vls + (size_t)r * SEQ + kb * 64 + (c - 16) * 8);
            cp16(sb + SV_OFF + r * APITCHB + c * 16, src);
        }
        cp_commit();
        cp_wait0();
        __syncthreads();

        // ---- S = Q' K'^T  (12 k-steps) ----
        float accs[4][4];
#pragma unroll
        for (int j = 0; j < 4; j++)
#pragma unroll
            for (int t = 0; t < 4; t++) accs[j][t] = 0.f;

#pragma unroll
        for (int ks_ = 0; ks_ < 12; ks_++) {
            uint32_t af[4], bf[4][2];
            ldmx4(af, sb + SQ_OFF + (wm * 16 + a_moff) * APITCHB + ks_ * 32 + a_half * 16);
#pragma unroll
            for (int jj = 0; jj < 2; jj++) {
                uint32_t r[4];
                ldmx4(r, sb + SK_OFF + (wn * 32 + jj * 16 + b_noff) * APITCHB
                         + ks_ * 32 + b_half * 16);
                bf[jj * 2][0] = r[0]; bf[jj * 2][1] = r[1];
                bf[jj * 2 + 1][0] = r[2]; bf[jj * 2 + 1][1] = r[3];
            }
#pragma unroll
            for (int fj = 0; fj < 4; fj++) mma16816(accs[fj], af, bf[fj]);
        }

        // causal mask (diagonal tile)
        if (kb == qb) {
#pragma unroll
            for (int fj = 0; fj < 4; fj++) {
                int gc = wn * 32 + fj * 8 + ecol;
                if (gc     > r0) accs[fj][0] = -1e30f;
                if (gc + 1 > r0) accs[fj][1] = -1e30f;
                if (gc     > r1) accs[fj][2] = -1e30f;
                if (gc + 1 > r1) accs[fj][3] = -1e30f;
            }
        }

        // ---- row maxes ----
        float lm0 = -1e30f, lm1 = -1e30f;
#pragma unroll
        for (int fj = 0; fj < 4; fj++) {
            lm0 = fmaxf(lm0, fmaxf(accs[fj][0], accs[fj][1]));
            lm1 = fmaxf(lm1, fmaxf(accs[fj][2], accs[fj][3]));
        }
        lm0 = fmaxf(lm0, __shfl_xor_sync(0xFFFFFFFF, lm0, 1));
        lm0 = fmaxf(lm0, __shfl_xor_sync(0xFFFFFFFF, lm0, 2));
        lm1 = fmaxf(lm1, __shfl_xor_sync(0xFFFFFFFF, lm1, 1));
        lm1 = fmaxf(lm1, __shfl_xor_sync(0xFFFFFFFF, lm1, 2));
        if ((lane & 3) == 0) {
            pmax[wn * 64 + r0] = lm0;
            pmax[wn * 64 + r1] = lm1;
        }
        __syncthreads();

        if (tid < 64) {
            float mo = mrow[tid];
            float mn = fmaxf(mo, fmaxf(pmax[tid], pmax[64 + tid]));
            mnew[tid] = mn;
            arow[tid] = __expf(mo - mn);
            mrow[tid] = mn;
        }
        __syncthreads();

        // ---- exp, write P' (hi|lo|hi), partial sums, rescale O ----
        const float mn0 = mnew[r0], mn1 = mnew[r1];
        const float al0 = arow[r0], al1 = arow[r1];
        float s0 = 0.f, s1 = 0.f;
#pragma unroll
        for (int fj = 0; fj < 4; fj++) {
            int kc = wn * 32 + fj * 8 + ecol;
            float p00 = __expf(accs[fj][0] - mn0);
            float p01 = __expf(accs[fj][1] - mn0);
            float p10 = __expf(accs[fj][2] - mn1);
            float p11 = __expf(accs[fj][3] - mn1);
            s0 += p00 + p01;
            s1 += p10 + p11;
            __nv_bfloat16 h00 = __float2bfloat16(p00), h01 = __float2bfloat16(p01);
            __nv_bfloat16 h10 = __float2bfloat16(p10), h11 = __float2bfloat16(p11);
            __nv_bfloat162 hp0 = __nv_bfloat162(h00, h01);
            __nv_bfloat162 hp1 = __nv_bfloat162(h10, h11);
            __nv_bfloat162 lp0 = __nv_bfloat162(
                __float2bfloat16(p00 - __bfloat162float(h00)),
                __float2bfloat16(p01 - __bfloat162float(h01)));
            __nv_bfloat162 lp1 = __nv_bfloat162(
                __float2bfloat16(p10 - __bfloat162float(h10)),
                __float2bfloat16(p11 - __bfloat162float(h11)));
            char* pr0 = sm + SP_OFF + r0 * APITCHB;
            char* pr1 = sm + SP_OFF + r1 * APITCHB;
            *(__nv_bfloat162*)(pr0 + kc * 2)       = hp0;
            *(__nv_bfloat162*)(pr0 + 128 + kc * 2) = lp0;
            *(__nv_bfloat162*)(pr0 + 256 + kc * 2) = hp0;
            *(__nv_bfloat162*)(pr1 + kc * 2)       = hp1;
            *(__nv_bfloat162*)(pr1 + 128 + kc * 2) = lp1;
            *(__nv_bfloat162*)(pr1 + 256 + kc * 2) = hp1;
        }
        s0 += __shfl_xor_sync(0xFFFFFFFF, s0, 1);
        s0 += __shfl_xor_sync(0xFFFFFFFF, s0, 2);
        s1 += __shfl_xor_sync(0xFFFFFFFF, s1, 1);
        s1 += __shfl_xor_sync(0xFFFFFFFF, s1, 2);
        if ((lane & 3) == 0) {
            psum[wn * 64 + r0] = s0;
            psum[wn * 64 + r1] = s1;
        }
#pragma unroll
        for (int fj = 0; fj < 4; fj++) {
            acco[fj][0] *= al0; acco[fj][1] *= al0;
            acco[fj][2] *= al1; acco[fj][3] *= al1;
        }
        __syncthreads();
        if (tid < 64)
            lrow[tid] = lrow[tid] * arow[tid] + psum[tid] + psum[64 + tid];

        // ---- O += P' VT'^T  (12 k-steps) ----
#pragma unroll
        for (int ks_ = 0; ks_ < 12; ks_++) {
            uint32_t af[4], bf[4][2];
            ldmx4(af, sb + SP_OFF + (wm * 16 + a_moff) * APITCHB + ks_ * 32 + a_half * 16);
#pragma unroll
            for (int jj = 0; jj < 2; jj++) {
                uint32_t r[4];
                ldmx4(r, sb + SV_OFF + (wn * 32 + jj * 16 + b_noff) * APITCHB
                         + ks_ * 32 + b_half * 16);
                bf[jj * 2][0] = r[0]; bf[jj * 2][1] = r[1];
                bf[jj * 2 + 1][0] = r[2]; bf[jj * 2 + 1][1] = r[3];
            }
#pragma unroll
            for (int fj = 0; fj < 4; fj++) mma16816(acco[fj], af, bf[fj]);
        }
        __syncthreads();
    }

    // ---- finalize: O /= l, write [b, qb*64+q, h*64+d] ----
    const int b = bh >> 4, h = bh & 15;
    const float il0 = 1.f / lrow[r0];
    const float il1 = 1.f / lrow[r1];
    const size_t grow0 = (size_t)(b * SEQ + qb * 64 + r0) * DMODEL;
    const size_t grow1 = (size_t)(b * SEQ + qb * 64 + r1) * DMODEL;
#pragma unroll
    for (int fj = 0; fj < 4; fj++) {
        int col = h * 64 + wn * 32 + fj * 8 + ecol;
        *(float2*)&out[grow0 + col] = make_float2(acco[fj][0] * il0, acco[fj][1] * il0);
        *(float2*)&out[grow1 + col] = make_float2(acco[fj][2] * il1, acco[fj][3] * il1);
    }
}

// ---------------------------------------------------------------------------
// Launch
// ---------------------------------------------------------------------------
extern "C" void kernel_launch(void* const* d_in, const int* in_sizes, int n_in,
                              void* d_out, int out_size)
{
    const float* Q   = (const float*)d_in[0];
    const float* K   = (const float*)d_in[1];
    const float* V   = (const float*)d_in[2];
    const float* W_Q = (const float*)d_in[4];
    const float* W_K = (const float*)d_in[5];
    const float* W_V = (const float*)d_in[6];
    const float* W_O = (const float*)d_in[7];
    float* out = (float*)d_out;

    float *pq, *pk, *pv, *pa;
    __nv_bfloat16 *pas, *pws, *pqs, *pks, *pvh, *pvl;
    cudaGetSymbolAddress((void**)&pq, g_q);
    cudaGetSymbolAddress((void**)&pk, g_k);
    cudaGetSymbolAddress((void**)&pv, g_v);
    cudaGetSymbolAddress((void**)&pa, g_attn);
    cudaGetSymbolAddress((void**)&pas, g_asplit);
    cudaGetSymbolAddress((void**)&pws, g_wsplit);
    cudaGetSymbolAddress((void**)&pqs, g_qs);
    cudaGetSymbolAddress((void**)&pks, g_ks);
    cudaGetSymbolAddress((void**)&pvh, g_vth);
    cudaGetSymbolAddress((void**)&pvl, g_vtl);

    cudaFuncSetAttribute(gemm_mma,
                         cudaFuncAttributeMaxDynamicSharedMemorySize, GEMM_SMEM);
    cudaFuncSetAttribute(attn_mma,
                         cudaFuncAttributeMaxDynamicSharedMemorySize, ATTN_SMEM);

    const int actBlocks = ROWS * DMODEL / 4 / 256;     // 4096
    const int wgtBlocks = DMODEL * DMODEL / 4 / 256;   // 1024
    const int qkBlocks  = ROWS * DMODEL / 2 / 256;     // 8192
    dim3 gg(DMODEL / GN, ROWS / GM);                   // (4, 32)

    // Projections
    split_kernel<<<actBlocks, 256>>>((const float4*)Q, pas, 1);
    split_kernel<<<wgtBlocks, 256>>>((const float4*)W_Q, pws, 0);
    gemm_mma<<<gg, 512, GEMM_SMEM>>>(pas, pws, pq);
    split_kernel<<<actBlocks, 256>>>((const float4*)K, pas, 1);
    split_kernel<<<wgtBlocks, 256>>>((const float4*)W_K, pws, 0);
    gemm_mma<<<gg, 512, GEMM_SMEM>>>(pas, pws, pk);
    split_kernel<<<actBlocks, 256>>>((const float4*)V, pas, 1);
    split_kernel<<<wgtBlocks, 256>>>((const float4*)W_V, pws, 0);
    gemm_mma<<<gg, 512, GEMM_SMEM>>>(pas, pws, pv);

    // Attention operand prep
    qk_split<<<qkBlocks, 256>>>(pq, pqs, 0.125f, 0);
    qk_split<<<qkBlocks, 256>>>(pk, pks, 1.0f, 1);
    vt_split<<<dim3(32, 32), 256>>>(pv, pvh, pvl);

    // Tensor-core attention
    attn_mma<<<dim3(SEQ / 64, BATCH * HEADS), 256, ATTN_SMEM>>>(pqs, pks, pvh, pvl, pa);

    // Output projection
    split_kernel<<<actBlocks, 256>>>((const float4*)pa, pas, 1);
    split_kernel<<<wgtBlocks, 256>>>((const float4*)W_O, pws, 0);
    gemm_mma<<<gg, 512, GEMM_SMEM>>>(pas, pws, out);
}